// round 3
// baseline (speedup 1.0000x reference)
#include <cuda_runtime.h>
#include <cuda_bf16.h>

// Problem constants
#define B_  4
#define S_  2048
#define D_  1024
#define H_  16
#define DK_ 64
#define FF_ 4096
#define M_  (B_ * S_)   // 8192

// ---------------------------------------------------------------------------
// Scratch (device globals; no allocation allowed)
// ---------------------------------------------------------------------------
__device__ float g_q[M_ * D_];
__device__ float g_k[M_ * D_];
__device__ float g_v[M_ * D_];
__device__ float g_attn[M_ * D_];
__device__ float g_tmp[M_ * D_];
__device__ float g_h[M_ * D_];
__device__ float g_ff[M_ * FF_];

// ---------------------------------------------------------------------------
// SGEMM: C[M,N] = A[M,K] @ B[K,N] (+ residual) (ReLU) (head-scatter output)
// BM=BN=128, BK=16, 256 threads, 8x8 per thread.
// ---------------------------------------------------------------------------
template <bool RELU, bool RESID, bool HEADOUT>
__global__ __launch_bounds__(256) void sgemm_k(
    const float* __restrict__ A, const float* __restrict__ Bm,
    const float* __restrict__ Res, float* __restrict__ C,
    int M, int N, int K)
{
    __shared__ float As[16][132];   // k-major, padded
    __shared__ float Bs[16][128];   // k-major

    const int tid = threadIdx.x;
    const int tx = tid & 15;        // 0..15 -> 8 cols
    const int ty = tid >> 4;        // 0..15 -> 8 rows
    const int m0 = blockIdx.y * 128;
    const int n0 = blockIdx.x * 128;

    const int aRow = tid >> 2;          // 0..63
    const int aCol = (tid & 3) << 2;    // 0,4,8,12
    const int bRow = tid >> 5;          // 0..7
    const int bCol = (tid & 31) << 2;   // 0..124

    const float* Ap = A + (size_t)(m0 + aRow) * K + aCol;
    const float* Bp = Bm + (size_t)bRow * N + n0 + bCol;

    float acc[8][8];
    #pragma unroll
    for (int i = 0; i < 8; i++)
        #pragma unroll
        for (int j = 0; j < 8; j++) acc[i][j] = 0.f;

    for (int k0 = 0; k0 < K; k0 += 16) {
        float4 a0 = *(const float4*)(Ap);
        float4 a1 = *(const float4*)(Ap + (size_t)64 * K);
        float4 b0 = *(const float4*)(Bp);
        float4 b1 = *(const float4*)(Bp + (size_t)8 * N);

        As[aCol + 0][aRow] = a0.x; As[aCol + 1][aRow] = a0.y;
        As[aCol + 2][aRow] = a0.z; As[aCol + 3][aRow] = a0.w;
        As[aCol + 0][aRow + 64] = a1.x; As[aCol + 1][aRow + 64] = a1.y;
        As[aCol + 2][aRow + 64] = a1.z; As[aCol + 3][aRow + 64] = a1.w;
        *(float4*)&Bs[bRow][bCol]     = b0;
        *(float4*)&Bs[bRow + 8][bCol] = b1;
        __syncthreads();

        #pragma unroll
        for (int k = 0; k < 16; k++) {
            float4 aa0 = *(const float4*)&As[k][ty * 8];
            float4 aa1 = *(const float4*)&As[k][ty * 8 + 4];
            float4 bb0 = *(const float4*)&Bs[k][tx * 8];
            float4 bb1 = *(const float4*)&Bs[k][tx * 8 + 4];
            float av[8] = {aa0.x, aa0.y, aa0.z, aa0.w, aa1.x, aa1.y, aa1.z, aa1.w};
            float bv[8] = {bb0.x, bb0.y, bb0.z, bb0.w, bb1.x, bb1.y, bb1.z, bb1.w};
            #pragma unroll
            for (int i = 0; i < 8; i++)
                #pragma unroll
                for (int j = 0; j < 8; j++)
                    acc[i][j] = fmaf(av[i], bv[j], acc[i][j]);
        }
        __syncthreads();
        Ap += 16;
        Bp += (size_t)16 * N;
    }

    #pragma unroll
    for (int i = 0; i < 8; i++) {
        const int m = m0 + ty * 8 + i;
        #pragma unroll
        for (int j = 0; j < 8; j++) {
            const int n = n0 + tx * 8 + j;
            float v = acc[i][j];
            if (RELU)  v = fmaxf(v, 0.f);
            if (RESID) v += Res[(size_t)m * N + n];
            if (HEADOUT) {
                // m = b*S + s ; n = h*DK + d  ->  [(b*H+h)*S + s]*DK + d
                const int b = m >> 11, s = m & (S_ - 1);
                const int h = n >> 6, d = n & (DK_ - 1);
                C[((size_t)(b * H_ + h) * S_ + s) * DK_ + d] = v;
            } else {
                C[(size_t)m * N + n] = v;
            }
        }
    }
}

// ---------------------------------------------------------------------------
// Flash attention: one block per (bh, q-tile of 64). BK=32, d=64, fp32.
// Thread layout: ty=tid/8 owns 2 rows, tx=tid%8 owns 4 score cols / 8 O cols.
// ---------------------------------------------------------------------------
__global__ __launch_bounds__(256) void flash_attn_k(
    const float* __restrict__ Q, const float* __restrict__ K,
    const float* __restrict__ V, float* __restrict__ O)
{
    __shared__ float Qt[64][68];  // [d][r]
    __shared__ float Kt[64][36];  // [d][c]
    __shared__ float Vs[32][68];  // [c][d]
    __shared__ float Pt[32][68];  // [c][r]

    const int tid = threadIdx.x;
    const int tx = tid & 7;     // 0..7
    const int ty = tid >> 3;    // 0..31
    const int qt = blockIdx.x;  // 0..31
    const int bh = blockIdx.y;  // 0..63

    const float* Qb = Q + ((size_t)bh * S_ + qt * 64) * DK_;
    const float* Kb = K + (size_t)bh * S_ * DK_;
    const float* Vb = V + (size_t)bh * S_ * DK_;

    // Load Q tile, transposed to [d][r]
    #pragma unroll
    for (int ld = 0; ld < 4; ld++) {
        int idx = tid + ld * 256;
        int r = idx >> 4, f = (idx & 15) << 2;
        float4 qv = *(const float4*)(Qb + r * DK_ + f);
        Qt[f + 0][r] = qv.x; Qt[f + 1][r] = qv.y;
        Qt[f + 2][r] = qv.z; Qt[f + 3][r] = qv.w;
    }

    float mrow[2] = {-1e30f, -1e30f};
    float lrow[2] = {0.f, 0.f};
    float o[2][8];
    #pragma unroll
    for (int i = 0; i < 2; i++)
        #pragma unroll
        for (int c = 0; c < 8; c++) o[i][c] = 0.f;

    for (int kt = 0; kt < S_ / 32; kt++) {
        __syncthreads();  // prev iteration reads done
        const float* Kp = Kb + (size_t)kt * 32 * DK_;
        const float* Vp = Vb + (size_t)kt * 32 * DK_;
        #pragma unroll
        for (int ld = 0; ld < 2; ld++) {
            int idx = tid + ld * 256;
            int r = idx >> 4, f = (idx & 15) << 2;
            float4 kv = *(const float4*)(Kp + r * DK_ + f);
            Kt[f + 0][r] = kv.x; Kt[f + 1][r] = kv.y;
            Kt[f + 2][r] = kv.z; Kt[f + 3][r] = kv.w;
            *(float4*)&Vs[r][f] = *(const float4*)(Vp + r * DK_ + f);
        }
        __syncthreads();

        // scores: s[2][4] = Q rows (ty*2..) x K cols (tx*4..)
        float s[2][4];
        #pragma unroll
        for (int i = 0; i < 2; i++)
            #pragma unroll
            for (int j = 0; j < 4; j++) s[i][j] = 0.f;

        #pragma unroll
        for (int kk = 0; kk < 64; kk++) {
            float2 a = *(const float2*)&Qt[kk][ty * 2];
            float4 b = *(const float4*)&Kt[kk][tx * 4];
            s[0][0] = fmaf(a.x, b.x, s[0][0]); s[0][1] = fmaf(a.x, b.y, s[0][1]);
            s[0][2] = fmaf(a.x, b.z, s[0][2]); s[0][3] = fmaf(a.x, b.w, s[0][3]);
            s[1][0] = fmaf(a.y, b.x, s[1][0]); s[1][1] = fmaf(a.y, b.y, s[1][1]);
            s[1][2] = fmaf(a.y, b.z, s[1][2]); s[1][3] = fmaf(a.y, b.w, s[1][3]);
        }
        #pragma unroll
        for (int i = 0; i < 2; i++)
            #pragma unroll
            for (int j = 0; j < 4; j++) s[i][j] *= 0.125f;  // 1/sqrt(64)

        // online softmax
        #pragma unroll
        for (int i = 0; i < 2; i++) {
            float tm = fmaxf(fmaxf(s[i][0], s[i][1]), fmaxf(s[i][2], s[i][3]));
            tm = fmaxf(tm, __shfl_xor_sync(0xffffffffu, tm, 1));
            tm = fmaxf(tm, __shfl_xor_sync(0xffffffffu, tm, 2));
            tm = fmaxf(tm, __shfl_xor_sync(0xffffffffu, tm, 4));
            float nm = fmaxf(mrow[i], tm);
            float fac = __expf(mrow[i] - nm);
            mrow[i] = nm;
            float rs = 0.f;
            #pragma unroll
            for (int j = 0; j < 4; j++) {
                float p = __expf(s[i][j] - nm);
                s[i][j] = p;
                rs += p;
            }
            rs += __shfl_xor_sync(0xffffffffu, rs, 1);
            rs += __shfl_xor_sync(0xffffffffu, rs, 2);
            rs += __shfl_xor_sync(0xffffffffu, rs, 4);
            lrow[i] = lrow[i] * fac + rs;
            #pragma unroll
            for (int c = 0; c < 8; c++) o[i][c] *= fac;
        }

        // write P transposed: [c][r]
        #pragma unroll
        for (int j = 0; j < 4; j++)
            *(float2*)&Pt[tx * 4 + j][ty * 2] = make_float2(s[0][j], s[1][j]);
        __syncthreads();

        // O += P @ V
        #pragma unroll
        for (int k = 0; k < 32; k++) {
            float2 a = *(const float2*)&Pt[k][ty * 2];
            float4 b0 = *(const float4*)&Vs[k][tx * 8];
            float4 b1 = *(const float4*)&Vs[k][tx * 8 + 4];
            float bv[8] = {b0.x, b0.y, b0.z, b0.w, b1.x, b1.y, b1.z, b1.w};
            #pragma unroll
            for (int c = 0; c < 8; c++) {
                o[0][c] = fmaf(a.x, bv[c], o[0][c]);
                o[1][c] = fmaf(a.y, bv[c], o[1][c]);
            }
        }
    }

    // epilogue: normalize and scatter to [B,S,D] with col = h*64 + d
    const int b = bh >> 4, h = bh & 15;
    #pragma unroll
    for (int i = 0; i < 2; i++) {
        float inv = 1.0f / lrow[i];
        int row = b * S_ + qt * 64 + ty * 2 + i;
        float* dst = O + (size_t)row * D_ + h * DK_ + tx * 8;
        float4 r0 = make_float4(o[i][0] * inv, o[i][1] * inv, o[i][2] * inv, o[i][3] * inv);
        float4 r1 = make_float4(o[i][4] * inv, o[i][5] * inv, o[i][6] * inv, o[i][7] * inv);
        *(float4*)dst = r0;
        *(float4*)(dst + 4) = r1;
    }
}

// ---------------------------------------------------------------------------
// LayerNorm: one block (256 threads) per row of 1024
// ---------------------------------------------------------------------------
__global__ __launch_bounds__(256) void layernorm_k(
    const float* __restrict__ X, const float* __restrict__ gam,
    const float* __restrict__ bet, float* __restrict__ Y)
{
    const int row = blockIdx.x;
    const int tid = threadIdx.x;
    float4 v = *(const float4*)(X + (size_t)row * D_ + tid * 4);
    float s = v.x + v.y + v.z + v.w;
    float q = v.x * v.x + v.y * v.y + v.z * v.z + v.w * v.w;
    #pragma unroll
    for (int off = 16; off >= 1; off >>= 1) {
        s += __shfl_xor_sync(0xffffffffu, s, off);
        q += __shfl_xor_sync(0xffffffffu, q, off);
    }
    __shared__ float ss[8], sq[8];
    if ((tid & 31) == 0) { ss[tid >> 5] = s; sq[tid >> 5] = q; }
    __syncthreads();
    float ts = 0.f, tq = 0.f;
    #pragma unroll
    for (int i = 0; i < 8; i++) { ts += ss[i]; tq += sq[i]; }
    const float mu = ts * (1.0f / D_);
    const float var = tq * (1.0f / D_) - mu * mu;
    const float rstd = rsqrtf(var + 1e-5f);
    float4 g4 = *(const float4*)(gam + tid * 4);
    float4 b4 = *(const float4*)(bet + tid * 4);
    float4 y;
    y.x = (v.x - mu) * rstd * g4.x + b4.x;
    y.y = (v.y - mu) * rstd * g4.y + b4.y;
    y.z = (v.z - mu) * rstd * g4.z + b4.z;
    y.w = (v.w - mu) * rstd * g4.w + b4.w;
    *(float4*)(Y + (size_t)row * D_ + tid * 4) = y;
}

// ---------------------------------------------------------------------------
// Launch
// ---------------------------------------------------------------------------
extern "C" void kernel_launch(void* const* d_in, const int* in_sizes, int n_in,
                              void* d_out, int out_size)
{
    const float* x     = (const float*)d_in[0];
    const float* Wq    = (const float*)d_in[1];
    const float* Wk    = (const float*)d_in[2];
    const float* Wv    = (const float*)d_in[3];
    const float* Wo    = (const float*)d_in[4];
    const float* Wfc1  = (const float*)d_in[5];
    const float* Wfc2  = (const float*)d_in[6];
    const float* ln1g  = (const float*)d_in[7];
    const float* ln1b  = (const float*)d_in[8];
    const float* ln2g  = (const float*)d_in[9];
    const float* ln2b  = (const float*)d_in[10];
    float* out = (float*)d_out;

    float *q, *k, *v, *attn, *tmp, *h, *ff;
    cudaGetSymbolAddress((void**)&q,    g_q);
    cudaGetSymbolAddress((void**)&k,    g_k);
    cudaGetSymbolAddress((void**)&v,    g_v);
    cudaGetSymbolAddress((void**)&attn, g_attn);
    cudaGetSymbolAddress((void**)&tmp,  g_tmp);
    cudaGetSymbolAddress((void**)&h,    g_h);
    cudaGetSymbolAddress((void**)&ff,   g_ff);

    dim3 blk(256);
    dim3 gD(D_ / 128, M_ / 128);    // (8, 64)
    dim3 gF(FF_ / 128, M_ / 128);   // (32, 64)

    // QKV projections with head-scatter epilogue
    sgemm_k<false, false, true><<<gD, blk>>>(x, Wq, nullptr, q, M_, D_, D_);
    sgemm_k<false, false, true><<<gD, blk>>>(x, Wk, nullptr, k, M_, D_, D_);
    sgemm_k<false, false, true><<<gD, blk>>>(x, Wv, nullptr, v, M_, D_, D_);

    // attention
    flash_attn_k<<<dim3(S_ / 64, B_ * H_), blk>>>(q, k, v, attn);

    // O projection + residual, LN1
    sgemm_k<false, true, false><<<gD, blk>>>(attn, Wo, x, tmp, M_, D_, D_);
    layernorm_k<<<M_, blk>>>(tmp, ln1g, ln1b, h);

    // FFN: fc1 (+ReLU), fc2 (+residual), LN2 -> out
    sgemm_k<true, false, false><<<gF, blk>>>(h, Wfc1, nullptr, ff, M_, FF_, D_);
    sgemm_k<false, true, false><<<gD, blk>>>(ff, Wfc2, h, tmp, M_, D_, FF_);
    layernorm_k<<<M_, blk>>>(tmp, ln2g, ln2b, out);
}

// round 4
// speedup vs baseline: 1.4141x; 1.4141x over previous
#include <cuda_runtime.h>
#include <cuda_bf16.h>

// Problem constants
#define B_  4
#define S_  2048
#define D_  1024
#define H_  16
#define DK_ 64
#define FF_ 4096
#define M_  (B_ * S_)   // 8192

// ---------------------------------------------------------------------------
// Scratch (device globals; no allocation allowed)
// ---------------------------------------------------------------------------
__device__ float g_q[M_ * D_];
__device__ float g_k[M_ * D_];
__device__ float g_v[M_ * D_];
__device__ float g_attn[M_ * D_];
__device__ float g_tmp[M_ * D_];
__device__ float g_h[M_ * D_];
__device__ float g_ff[M_ * FF_];

__device__ __forceinline__ float to_tf32(float x) {
    float r;
    asm("cvt.rna.tf32.f32 %0, %1;" : "=f"(r) : "f"(x));
    return r;
}

__device__ __forceinline__ void mma_tf32(float* d, const float* a, const float* b) {
    asm volatile(
        "mma.sync.aligned.m16n8k8.row.col.f32.tf32.tf32.f32 "
        "{%0,%1,%2,%3}, {%4,%5,%6,%7}, {%8,%9}, {%0,%1,%2,%3};"
        : "+f"(d[0]), "+f"(d[1]), "+f"(d[2]), "+f"(d[3])
        : "r"(__float_as_uint(a[0])), "r"(__float_as_uint(a[1])),
          "r"(__float_as_uint(a[2])), "r"(__float_as_uint(a[3])),
          "r"(__float_as_uint(b[0])), "r"(__float_as_uint(b[1])));
}

// ---------------------------------------------------------------------------
// TF32 tensor-core GEMM: C[M,N] = A[M,K] @ B[K,N] (+res)(relu)(head-scatter)
// 128x128 block tile, BK=32, 256 threads (8 warps), warp tile 64x32.
// ---------------------------------------------------------------------------
template <bool RELU, bool RESID, bool HEADOUT>
__global__ __launch_bounds__(256) void tf32gemm_k(
    const float* __restrict__ A, const float* __restrict__ Bm,
    const float* __restrict__ Res, float* __restrict__ C,
    int M, int N, int K)
{
    __shared__ float As[128][36];   // [row][k], pad 36 -> frag LDS conflict-free
    __shared__ float Bs[32][136];   // [k][col], pad 136 -> frag LDS conflict-free

    const int tid  = threadIdx.x;
    const int lane = tid & 31;
    const int wid  = tid >> 5;        // 0..7
    const int wm   = wid & 1;         // warp row: 0..1  (64 rows each)
    const int wn   = wid >> 1;        // warp col: 0..3  (32 cols each)
    const int gid  = lane >> 2;       // 0..7
    const int qid  = lane & 3;        // 0..3

    const int m0 = blockIdx.y * 128;
    const int n0 = blockIdx.x * 128;

    // Global->smem mapping
    const int aRow = tid >> 1;            // 0..127
    const int aHalf = (tid & 1) * 16;     // 0 or 16
    const int bRow = tid >> 3;            // 0..31
    const int bCol = (tid & 7) * 16;      // 0..112

    const float* Ap = A + (size_t)(m0 + aRow) * K + aHalf;
    const float* Bp = Bm + (size_t)bRow * N + n0 + bCol;

    float acc[4][4][4];
    #pragma unroll
    for (int i = 0; i < 4; i++)
        #pragma unroll
        for (int j = 0; j < 4; j++)
            #pragma unroll
            for (int r = 0; r < 4; r++) acc[i][j][r] = 0.f;

    for (int k0 = 0; k0 < K; k0 += 32) {
        // load gmem
        float4 av[4], bv[4];
        #pragma unroll
        for (int i = 0; i < 4; i++) av[i] = *(const float4*)(Ap + i * 4);
        #pragma unroll
        for (int i = 0; i < 4; i++) bv[i] = *(const float4*)(Bp + i * 4);

        __syncthreads();  // protect previous iteration's reads
        #pragma unroll
        for (int i = 0; i < 4; i++) {
            float4 t;
            t.x = to_tf32(av[i].x); t.y = to_tf32(av[i].y);
            t.z = to_tf32(av[i].z); t.w = to_tf32(av[i].w);
            *(float4*)&As[aRow][aHalf + i * 4] = t;
        }
        #pragma unroll
        for (int i = 0; i < 4; i++) {
            float4 t;
            t.x = to_tf32(bv[i].x); t.y = to_tf32(bv[i].y);
            t.z = to_tf32(bv[i].z); t.w = to_tf32(bv[i].w);
            *(float4*)&Bs[bRow][bCol + i * 4] = t;
        }
        __syncthreads();

        #pragma unroll
        for (int ks = 0; ks < 4; ks++) {
            const int kb = ks * 8;
            float af[4][4], bf[4][2];
            #pragma unroll
            for (int mt = 0; mt < 4; mt++) {
                const int r = wm * 64 + mt * 16 + gid;
                af[mt][0] = As[r][kb + qid];
                af[mt][1] = As[r + 8][kb + qid];
                af[mt][2] = As[r][kb + qid + 4];
                af[mt][3] = As[r + 8][kb + qid + 4];
            }
            #pragma unroll
            for (int nt = 0; nt < 4; nt++) {
                const int c = wn * 32 + nt * 8 + gid;
                bf[nt][0] = Bs[kb + qid][c];
                bf[nt][1] = Bs[kb + qid + 4][c];
            }
            #pragma unroll
            for (int mt = 0; mt < 4; mt++)
                #pragma unroll
                for (int nt = 0; nt < 4; nt++)
                    mma_tf32(acc[mt][nt], af[mt], bf[nt]);
        }

        Ap += 32;
        Bp += (size_t)32 * N;
    }

    // epilogue: c0,c1 at (row, col..col+1), c2,c3 at (row+8, ...)
    #pragma unroll
    for (int mt = 0; mt < 4; mt++) {
        #pragma unroll
        for (int nt = 0; nt < 4; nt++) {
            const int rBase = m0 + wm * 64 + mt * 16 + gid;
            const int cBase = n0 + wn * 32 + nt * 8 + qid * 2;
            #pragma unroll
            for (int half = 0; half < 2; half++) {
                const int m = rBase + half * 8;
                float v0 = acc[mt][nt][half * 2 + 0];
                float v1 = acc[mt][nt][half * 2 + 1];
                if (RELU)  { v0 = fmaxf(v0, 0.f); v1 = fmaxf(v1, 0.f); }
                if (RESID) {
                    const float* rp = Res + (size_t)m * N + cBase;
                    v0 += rp[0]; v1 += rp[1];
                }
                if (HEADOUT) {
                    // m = b*S + s ; n = h*DK + d -> [(b*H+h)*S + s]*DK + d
                    const int b = m >> 11, s = m & (S_ - 1);
                    const int h = cBase >> 6, d = cBase & (DK_ - 1);
                    float* dst = C + ((size_t)(b * H_ + h) * S_ + s) * DK_ + d;
                    dst[0] = v0; dst[1] = v1;
                } else {
                    float* dst = C + (size_t)m * N + cBase;
                    dst[0] = v0; dst[1] = v1;
                }
            }
        }
    }
}

// ---------------------------------------------------------------------------
// Flash attention: one block per (bh, q-tile of 64). BK=32, d=64, fp32.
// ---------------------------------------------------------------------------
__global__ __launch_bounds__(256) void flash_attn_k(
    const float* __restrict__ Q, const float* __restrict__ K,
    const float* __restrict__ V, float* __restrict__ O)
{
    __shared__ float Qt[64][68];  // [d][r]
    __shared__ float Kt[64][36];  // [d][c]
    __shared__ float Vs[32][68];  // [c][d]
    __shared__ float Pt[32][68];  // [c][r]

    const int tid = threadIdx.x;
    const int tx = tid & 7;     // 0..7
    const int ty = tid >> 3;    // 0..31
    const int qt = blockIdx.x;  // 0..31
    const int bh = blockIdx.y;  // 0..63

    const float* Qb = Q + ((size_t)bh * S_ + qt * 64) * DK_;
    const float* Kb = K + (size_t)bh * S_ * DK_;
    const float* Vb = V + (size_t)bh * S_ * DK_;

    #pragma unroll
    for (int ld = 0; ld < 4; ld++) {
        int idx = tid + ld * 256;
        int r = idx >> 4, f = (idx & 15) << 2;
        float4 qv = *(const float4*)(Qb + r * DK_ + f);
        Qt[f + 0][r] = qv.x; Qt[f + 1][r] = qv.y;
        Qt[f + 2][r] = qv.z; Qt[f + 3][r] = qv.w;
    }

    float mrow[2] = {-1e30f, -1e30f};
    float lrow[2] = {0.f, 0.f};
    float o[2][8];
    #pragma unroll
    for (int i = 0; i < 2; i++)
        #pragma unroll
        for (int c = 0; c < 8; c++) o[i][c] = 0.f;

    for (int kt = 0; kt < S_ / 32; kt++) {
        __syncthreads();
        const float* Kp = Kb + (size_t)kt * 32 * DK_;
        const float* Vp = Vb + (size_t)kt * 32 * DK_;
        #pragma unroll
        for (int ld = 0; ld < 2; ld++) {
            int idx = tid + ld * 256;
            int r = idx >> 4, f = (idx & 15) << 2;
            float4 kv = *(const float4*)(Kp + r * DK_ + f);
            Kt[f + 0][r] = kv.x; Kt[f + 1][r] = kv.y;
            Kt[f + 2][r] = kv.z; Kt[f + 3][r] = kv.w;
            *(float4*)&Vs[r][f] = *(const float4*)(Vp + r * DK_ + f);
        }
        __syncthreads();

        float s[2][4];
        #pragma unroll
        for (int i = 0; i < 2; i++)
            #pragma unroll
            for (int j = 0; j < 4; j++) s[i][j] = 0.f;

        #pragma unroll
        for (int kk = 0; kk < 64; kk++) {
            float2 a = *(const float2*)&Qt[kk][ty * 2];
            float4 b = *(const float4*)&Kt[kk][tx * 4];
            s[0][0] = fmaf(a.x, b.x, s[0][0]); s[0][1] = fmaf(a.x, b.y, s[0][1]);
            s[0][2] = fmaf(a.x, b.z, s[0][2]); s[0][3] = fmaf(a.x, b.w, s[0][3]);
            s[1][0] = fmaf(a.y, b.x, s[1][0]); s[1][1] = fmaf(a.y, b.y, s[1][1]);
            s[1][2] = fmaf(a.y, b.z, s[1][2]); s[1][3] = fmaf(a.y, b.w, s[1][3]);
        }
        #pragma unroll
        for (int i = 0; i < 2; i++)
            #pragma unroll
            for (int j = 0; j < 4; j++) s[i][j] *= 0.125f;

        #pragma unroll
        for (int i = 0; i < 2; i++) {
            float tm = fmaxf(fmaxf(s[i][0], s[i][1]), fmaxf(s[i][2], s[i][3]));
            tm = fmaxf(tm, __shfl_xor_sync(0xffffffffu, tm, 1));
            tm = fmaxf(tm, __shfl_xor_sync(0xffffffffu, tm, 2));
            tm = fmaxf(tm, __shfl_xor_sync(0xffffffffu, tm, 4));
            float nm = fmaxf(mrow[i], tm);
            float fac = __expf(mrow[i] - nm);
            mrow[i] = nm;
            float rs = 0.f;
            #pragma unroll
            for (int j = 0; j < 4; j++) {
                float p = __expf(s[i][j] - nm);
                s[i][j] = p;
                rs += p;
            }
            rs += __shfl_xor_sync(0xffffffffu, rs, 1);
            rs += __shfl_xor_sync(0xffffffffu, rs, 2);
            rs += __shfl_xor_sync(0xffffffffu, rs, 4);
            lrow[i] = lrow[i] * fac + rs;
            #pragma unroll
            for (int c = 0; c < 8; c++) o[i][c] *= fac;
        }

        #pragma unroll
        for (int j = 0; j < 4; j++)
            *(float2*)&Pt[tx * 4 + j][ty * 2] = make_float2(s[0][j], s[1][j]);
        __syncthreads();

        #pragma unroll
        for (int k = 0; k < 32; k++) {
            float2 a = *(const float2*)&Pt[k][ty * 2];
            float4 b0 = *(const float4*)&Vs[k][tx * 8];
            float4 b1 = *(const float4*)&Vs[k][tx * 8 + 4];
            float bv[8] = {b0.x, b0.y, b0.z, b0.w, b1.x, b1.y, b1.z, b1.w};
            #pragma unroll
            for (int c = 0; c < 8; c++) {
                o[0][c] = fmaf(a.x, bv[c], o[0][c]);
                o[1][c] = fmaf(a.y, bv[c], o[1][c]);
            }
        }
    }

    const int b = bh >> 4, h = bh & 15;
    #pragma unroll
    for (int i = 0; i < 2; i++) {
        float inv = 1.0f / lrow[i];
        int row = b * S_ + qt * 64 + ty * 2 + i;
        float* dst = O + (size_t)row * D_ + h * DK_ + tx * 8;
        float4 r0 = make_float4(o[i][0] * inv, o[i][1] * inv, o[i][2] * inv, o[i][3] * inv);
        float4 r1 = make_float4(o[i][4] * inv, o[i][5] * inv, o[i][6] * inv, o[i][7] * inv);
        *(float4*)dst = r0;
        *(float4*)(dst + 4) = r1;
    }
}

// ---------------------------------------------------------------------------
// LayerNorm: one block (256 threads) per row of 1024
// ---------------------------------------------------------------------------
__global__ __launch_bounds__(256) void layernorm_k(
    const float* __restrict__ X, const float* __restrict__ gam,
    const float* __restrict__ bet, float* __restrict__ Y)
{
    const int row = blockIdx.x;
    const int tid = threadIdx.x;
    float4 v = *(const float4*)(X + (size_t)row * D_ + tid * 4);
    float s = v.x + v.y + v.z + v.w;
    float q = v.x * v.x + v.y * v.y + v.z * v.z + v.w * v.w;
    #pragma unroll
    for (int off = 16; off >= 1; off >>= 1) {
        s += __shfl_xor_sync(0xffffffffu, s, off);
        q += __shfl_xor_sync(0xffffffffu, q, off);
    }
    __shared__ float ss[8], sq[8];
    if ((tid & 31) == 0) { ss[tid >> 5] = s; sq[tid >> 5] = q; }
    __syncthreads();
    float ts = 0.f, tq = 0.f;
    #pragma unroll
    for (int i = 0; i < 8; i++) { ts += ss[i]; tq += sq[i]; }
    const float mu = ts * (1.0f / D_);
    const float var = tq * (1.0f / D_) - mu * mu;
    const float rstd = rsqrtf(var + 1e-5f);
    float4 g4 = *(const float4*)(gam + tid * 4);
    float4 b4 = *(const float4*)(bet + tid * 4);
    float4 y;
    y.x = (v.x - mu) * rstd * g4.x + b4.x;
    y.y = (v.y - mu) * rstd * g4.y + b4.y;
    y.z = (v.z - mu) * rstd * g4.z + b4.z;
    y.w = (v.w - mu) * rstd * g4.w + b4.w;
    *(float4*)(Y + (size_t)row * D_ + tid * 4) = y;
}

// ---------------------------------------------------------------------------
// Launch
// ---------------------------------------------------------------------------
extern "C" void kernel_launch(void* const* d_in, const int* in_sizes, int n_in,
                              void* d_out, int out_size)
{
    const float* x     = (const float*)d_in[0];
    const float* Wq    = (const float*)d_in[1];
    const float* Wk    = (const float*)d_in[2];
    const float* Wv    = (const float*)d_in[3];
    const float* Wo    = (const float*)d_in[4];
    const float* Wfc1  = (const float*)d_in[5];
    const float* Wfc2  = (const float*)d_in[6];
    const float* ln1g  = (const float*)d_in[7];
    const float* ln1b  = (const float*)d_in[8];
    const float* ln2g  = (const float*)d_in[9];
    const float* ln2b  = (const float*)d_in[10];
    float* out = (float*)d_out;

    float *q, *k, *v, *attn, *tmp, *h, *ff;
    cudaGetSymbolAddress((void**)&q,    g_q);
    cudaGetSymbolAddress((void**)&k,    g_k);
    cudaGetSymbolAddress((void**)&v,    g_v);
    cudaGetSymbolAddress((void**)&attn, g_attn);
    cudaGetSymbolAddress((void**)&tmp,  g_tmp);
    cudaGetSymbolAddress((void**)&h,    g_h);
    cudaGetSymbolAddress((void**)&ff,   g_ff);

    dim3 blk(256);
    dim3 gD(D_ / 128, M_ / 128);    // (8, 64)
    dim3 gF(FF_ / 128, M_ / 128);   // (32, 64)

    // QKV projections with head-scatter epilogue (TF32 tensor cores)
    tf32gemm_k<false, false, true><<<gD, blk>>>(x, Wq, nullptr, q, M_, D_, D_);
    tf32gemm_k<false, false, true><<<gD, blk>>>(x, Wk, nullptr, k, M_, D_, D_);
    tf32gemm_k<false, false, true><<<gD, blk>>>(x, Wv, nullptr, v, M_, D_, D_);

    // attention
    flash_attn_k<<<dim3(S_ / 64, B_ * H_), blk>>>(q, k, v, attn);

    // O projection + residual, LN1
    tf32gemm_k<false, true, false><<<gD, blk>>>(attn, Wo, x, tmp, M_, D_, D_);
    layernorm_k<<<M_, blk>>>(tmp, ln1g, ln1b, h);

    // FFN: fc1 (+ReLU), fc2 (+residual), LN2 -> out
    tf32gemm_k<true, false, false><<<gF, blk>>>(h, Wfc1, nullptr, ff, M_, FF_, D_);
    tf32gemm_k<false, true, false><<<gD, blk>>>(ff, Wfc2, h, tmp, M_, D_, FF_);
    layernorm_k<<<M_, blk>>>(tmp, ln2g, ln2b, out);
}

// round 6
// speedup vs baseline: 2.8448x; 2.0118x over previous
#include <cuda_runtime.h>
#include <cuda_bf16.h>

// Problem constants
#define B_  4
#define S_  2048
#define D_  1024
#define H_  16
#define DK_ 64
#define FF_ 4096
#define M_  (B_ * S_)   // 8192

// ---------------------------------------------------------------------------
// Scratch (device globals; no allocation allowed)
// ---------------------------------------------------------------------------
__device__ float g_q[M_ * D_];
__device__ float g_k[M_ * D_];
__device__ float g_v[M_ * D_];
__device__ float g_attn[M_ * D_];
__device__ float g_tmp[M_ * D_];
__device__ float g_h[M_ * D_];
__device__ float g_ff[M_ * FF_];

__device__ __forceinline__ float to_tf32(float x) {
    float r;
    asm("cvt.rna.tf32.f32 %0, %1;" : "=f"(r) : "f"(x));
    return r;
}

__device__ __forceinline__ void mma_tf32(float* d, const float* a, const float* b) {
    asm volatile(
        "mma.sync.aligned.m16n8k8.row.col.f32.tf32.tf32.f32 "
        "{%0,%1,%2,%3}, {%4,%5,%6,%7}, {%8,%9}, {%0,%1,%2,%3};"
        : "+f"(d[0]), "+f"(d[1]), "+f"(d[2]), "+f"(d[3])
        : "r"(__float_as_uint(a[0])), "r"(__float_as_uint(a[1])),
          "r"(__float_as_uint(a[2])), "r"(__float_as_uint(a[3])),
          "r"(__float_as_uint(b[0])), "r"(__float_as_uint(b[1])));
}

// ---------------------------------------------------------------------------
// TF32 tensor-core GEMM: C[M,N] = A[M,K] @ B[K,N] (+res)(relu)(head-scatter)
// 128x128 block tile, BK=32, 256 threads (8 warps), warp tile 64x32.
// Register-prefetch mainloop: LDG for tile k+1 overlaps mma on tile k.
// ---------------------------------------------------------------------------
template <bool RELU, bool RESID, bool HEADOUT>
__global__ __launch_bounds__(256) void tf32gemm_k(
    const float* __restrict__ A, const float* __restrict__ Bm,
    const float* __restrict__ Res, float* __restrict__ C,
    int M, int N, int K)
{
    __shared__ float As[128][36];   // [row][k], pad 36 -> frag LDS conflict-free
    __shared__ float Bs[32][136];   // [k][col], pad 136 -> frag LDS conflict-free

    const int tid  = threadIdx.x;
    const int lane = tid & 31;
    const int wid  = tid >> 5;        // 0..7
    const int wm   = wid & 1;         // warp row: 0..1  (64 rows each)
    const int wn   = wid >> 1;        // warp col: 0..3  (32 cols each)
    const int gid  = lane >> 2;       // 0..7
    const int qid  = lane & 3;        // 0..3

    const int m0 = blockIdx.y * 128;
    const int n0 = blockIdx.x * 128;

    const int aRow = tid >> 1;            // 0..127
    const int aHalf = (tid & 1) * 16;     // 0 or 16
    const int bRow = tid >> 3;            // 0..31
    const int bCol = (tid & 7) * 16;      // 0..112

    const float* Ap = A + (size_t)(m0 + aRow) * K + aHalf;
    const float* Bp = Bm + (size_t)bRow * N + n0 + bCol;

    float acc[4][4][4];
    #pragma unroll
    for (int i = 0; i < 4; i++)
        #pragma unroll
        for (int j = 0; j < 4; j++)
            #pragma unroll
            for (int r = 0; r < 4; r++) acc[i][j][r] = 0.f;

    // prologue: prefetch first tile into registers
    float4 av[4], bv[4];
    #pragma unroll
    for (int i = 0; i < 4; i++) av[i] = *(const float4*)(Ap + i * 4);
    #pragma unroll
    for (int i = 0; i < 4; i++) bv[i] = *(const float4*)(Bp + i * 4);

    for (int k0 = 0; k0 < K; k0 += 32) {
        // store current tile regs -> smem (with tf32 round)
        #pragma unroll
        for (int i = 0; i < 4; i++) {
            float4 t;
            t.x = to_tf32(av[i].x); t.y = to_tf32(av[i].y);
            t.z = to_tf32(av[i].z); t.w = to_tf32(av[i].w);
            *(float4*)&As[aRow][aHalf + i * 4] = t;
        }
        #pragma unroll
        for (int i = 0; i < 4; i++) {
            float4 t;
            t.x = to_tf32(bv[i].x); t.y = to_tf32(bv[i].y);
            t.z = to_tf32(bv[i].z); t.w = to_tf32(bv[i].w);
            *(float4*)&Bs[bRow][bCol + i * 4] = t;
        }
        __syncthreads();

        // prefetch next tile (LDG overlaps the mma work below)
        if (k0 + 32 < K) {
            Ap += 32;
            Bp += (size_t)32 * N;
            #pragma unroll
            for (int i = 0; i < 4; i++) av[i] = *(const float4*)(Ap + i * 4);
            #pragma unroll
            for (int i = 0; i < 4; i++) bv[i] = *(const float4*)(Bp + i * 4);
        }

        #pragma unroll
        for (int ks = 0; ks < 4; ks++) {
            const int kb = ks * 8;
            float af[4][4], bf[4][2];
            #pragma unroll
            for (int mt = 0; mt < 4; mt++) {
                const int r = wm * 64 + mt * 16 + gid;
                af[mt][0] = As[r][kb + qid];
                af[mt][1] = As[r + 8][kb + qid];
                af[mt][2] = As[r][kb + qid + 4];
                af[mt][3] = As[r + 8][kb + qid + 4];
            }
            #pragma unroll
            for (int nt = 0; nt < 4; nt++) {
                const int c = wn * 32 + nt * 8 + gid;
                bf[nt][0] = Bs[kb + qid][c];
                bf[nt][1] = Bs[kb + qid + 4][c];
            }
            #pragma unroll
            for (int mt = 0; mt < 4; mt++)
                #pragma unroll
                for (int nt = 0; nt < 4; nt++)
                    mma_tf32(acc[mt][nt], af[mt], bf[nt]);
        }
        __syncthreads();
    }

    // epilogue
    #pragma unroll
    for (int mt = 0; mt < 4; mt++) {
        #pragma unroll
        for (int nt = 0; nt < 4; nt++) {
            const int rBase = m0 + wm * 64 + mt * 16 + gid;
            const int cBase = n0 + wn * 32 + nt * 8 + qid * 2;
            #pragma unroll
            for (int half = 0; half < 2; half++) {
                const int m = rBase + half * 8;
                float v0 = acc[mt][nt][half * 2 + 0];
                float v1 = acc[mt][nt][half * 2 + 1];
                if (RELU)  { v0 = fmaxf(v0, 0.f); v1 = fmaxf(v1, 0.f); }
                if (RESID) {
                    const float* rp = Res + (size_t)m * N + cBase;
                    v0 += rp[0]; v1 += rp[1];
                }
                if (HEADOUT) {
                    const int b = m >> 11, s = m & (S_ - 1);
                    const int h = cBase >> 6, d = cBase & (DK_ - 1);
                    float* dst = C + ((size_t)(b * H_ + h) * S_ + s) * DK_ + d;
                    dst[0] = v0; dst[1] = v1;
                } else {
                    float* dst = C + (size_t)m * N + cBase;
                    dst[0] = v0; dst[1] = v1;
                }
            }
        }
    }
}

// ---------------------------------------------------------------------------
// TF32 mma flash attention. One block per (bh, q-tile of 64).
// 128 threads = 4 warps; warp w owns q rows [w*16, w*16+16).
// Key tile = 32, d = 64. Online softmax in registers.
// ---------------------------------------------------------------------------
__global__ __launch_bounds__(128) void flash_attn_mma_k(
    const float* __restrict__ Q, const float* __restrict__ K,
    const float* __restrict__ V, float* __restrict__ O)
{
    __shared__ float Qs[64][68];   // [q][d]   banks: 4*gid+qid (A frags)
    __shared__ float Ks[32][68];   // [key][d] banks: 4*gid+qid (B frags QK)
    __shared__ float Vs[32][72];   // [key][d] banks: 8*qid+gid (B frags PV)
    __shared__ float Ps[64][36];   // [q][key] banks: 4*gid+qid (A frags PV)

    const int tid  = threadIdx.x;
    const int lane = tid & 31;
    const int wid  = tid >> 5;     // 0..3
    const int gid  = lane >> 2;    // 0..7
    const int qid  = lane & 3;     // 0..3
    const int wq0  = wid * 16;

    const int qt = blockIdx.x;     // 0..31
    const int bh = blockIdx.y;     // 0..63

    const float* Qb = Q + ((size_t)bh * S_ + qt * 64) * DK_;
    const float* Kb = K + (size_t)bh * S_ * DK_;
    const float* Vb = V + (size_t)bh * S_ * DK_;

    // Load Q tile (fold in 1/sqrt(dk)=0.125, round to tf32): 8 float4/thread
    #pragma unroll
    for (int i = 0; i < 8; i++) {
        int idx = tid + i * 128;
        int r = idx >> 4, f = (idx & 15) << 2;
        float4 v = *(const float4*)(Qb + r * DK_ + f);
        float4 t;
        t.x = to_tf32(v.x * 0.125f); t.y = to_tf32(v.y * 0.125f);
        t.z = to_tf32(v.z * 0.125f); t.w = to_tf32(v.w * 0.125f);
        *(float4*)&Qs[r][f] = t;
    }

    float oacc[8][4];
    #pragma unroll
    for (int nt = 0; nt < 8; nt++)
        #pragma unroll
        for (int r = 0; r < 4; r++) oacc[nt][r] = 0.f;
    float mrow[2] = {-1e30f, -1e30f};
    float lrow[2] = {0.f, 0.f};

    for (int kt = 0; kt < S_ / 32; kt++) {
        __syncthreads();  // prev-iter Ks/Vs reads done
        const float* Kp = Kb + (size_t)kt * 32 * DK_;
        const float* Vp = Vb + (size_t)kt * 32 * DK_;
        #pragma unroll
        for (int i = 0; i < 4; i++) {
            int idx = tid + i * 128;
            int r = idx >> 4, f = (idx & 15) << 2;
            float4 kv = *(const float4*)(Kp + r * DK_ + f);
            float4 tk;
            tk.x = to_tf32(kv.x); tk.y = to_tf32(kv.y);
            tk.z = to_tf32(kv.z); tk.w = to_tf32(kv.w);
            *(float4*)&Ks[r][f] = tk;
            float4 vv = *(const float4*)(Vp + r * DK_ + f);
            float4 tv;
            tv.x = to_tf32(vv.x); tv.y = to_tf32(vv.y);
            tv.z = to_tf32(vv.z); tv.w = to_tf32(vv.w);
            *(float4*)&Vs[r][f] = tv;
        }
        __syncthreads();

        // S = Q K^T : warp slab 16 q x 32 keys = 4 m16n8 tiles, k = 64
        float sacc[4][4];
        #pragma unroll
        for (int nt = 0; nt < 4; nt++)
            #pragma unroll
            for (int r = 0; r < 4; r++) sacc[nt][r] = 0.f;

        #pragma unroll
        for (int ks = 0; ks < 8; ks++) {
            const int kb = ks * 8;
            float af[4];
            af[0] = Qs[wq0 + gid][kb + qid];
            af[1] = Qs[wq0 + gid + 8][kb + qid];
            af[2] = Qs[wq0 + gid][kb + qid + 4];
            af[3] = Qs[wq0 + gid + 8][kb + qid + 4];
            #pragma unroll
            for (int nt = 0; nt < 4; nt++) {
                float bf[2];
                bf[0] = Ks[nt * 8 + gid][kb + qid];
                bf[1] = Ks[nt * 8 + gid][kb + qid + 4];
                mma_tf32(sacc[nt], af, bf);
            }
        }

        // online softmax: thread holds rows (gid, gid+8), 8 cols each
        #pragma unroll
        for (int i = 0; i < 2; i++) {
            const int b0 = i * 2;
            float tm = -1e30f;
            #pragma unroll
            for (int nt = 0; nt < 4; nt++)
                tm = fmaxf(tm, fmaxf(sacc[nt][b0], sacc[nt][b0 + 1]));
            tm = fmaxf(tm, __shfl_xor_sync(0xffffffffu, tm, 1));
            tm = fmaxf(tm, __shfl_xor_sync(0xffffffffu, tm, 2));
            float nm = fmaxf(mrow[i], tm);
            float fac = __expf(mrow[i] - nm);
            mrow[i] = nm;
            float rs = 0.f;
            #pragma unroll
            for (int nt = 0; nt < 4; nt++) {
                float p0 = __expf(sacc[nt][b0] - nm);
                float p1 = __expf(sacc[nt][b0 + 1] - nm);
                sacc[nt][b0] = p0; sacc[nt][b0 + 1] = p1;
                rs += p0 + p1;
            }
            rs += __shfl_xor_sync(0xffffffffu, rs, 1);
            rs += __shfl_xor_sync(0xffffffffu, rs, 2);
            lrow[i] = lrow[i] * fac + rs;
            #pragma unroll
            for (int nt = 0; nt < 8; nt++) {
                oacc[nt][b0] *= fac;
                oacc[nt][b0 + 1] *= fac;
            }
        }

        // write P slab (own warp rows only), tf32-rounded
        #pragma unroll
        for (int nt = 0; nt < 4; nt++) {
            *(float2*)&Ps[wq0 + gid][nt * 8 + qid * 2] =
                make_float2(to_tf32(sacc[nt][0]), to_tf32(sacc[nt][1]));
            *(float2*)&Ps[wq0 + gid + 8][nt * 8 + qid * 2] =
                make_float2(to_tf32(sacc[nt][2]), to_tf32(sacc[nt][3]));
        }
        __syncwarp();

        // O += P V : 16 q x 64 d = 8 m16n8 tiles, k = 32 keys
        #pragma unroll
        for (int ks = 0; ks < 4; ks++) {
            const int kb = ks * 8;
            float af[4];
            af[0] = Ps[wq0 + gid][kb + qid];
            af[1] = Ps[wq0 + gid + 8][kb + qid];
            af[2] = Ps[wq0 + gid][kb + qid + 4];
            af[3] = Ps[wq0 + gid + 8][kb + qid + 4];
            #pragma unroll
            for (int nt = 0; nt < 8; nt++) {
                float bf[2];
                bf[0] = Vs[kb + qid][nt * 8 + gid];
                bf[1] = Vs[kb + qid + 4][nt * 8 + gid];
                mma_tf32(oacc[nt], af, bf);
            }
        }
    }

    // epilogue: normalize, scatter to [B,S,D] at col h*64+d
    const int b = bh >> 4, h = bh & 15;
    #pragma unroll
    for (int i = 0; i < 2; i++) {
        float inv = 1.0f / lrow[i];
        int row = b * S_ + qt * 64 + wq0 + gid + i * 8;
        float* dst = O + (size_t)row * D_ + h * DK_;
        #pragma unroll
        for (int nt = 0; nt < 8; nt++) {
            *(float2*)&dst[nt * 8 + qid * 2] =
                make_float2(oacc[nt][i * 2] * inv, oacc[nt][i * 2 + 1] * inv);
        }
    }
}

// ---------------------------------------------------------------------------
// LayerNorm: one block (256 threads) per row of 1024
// ---------------------------------------------------------------------------
__global__ __launch_bounds__(256) void layernorm_k(
    const float* __restrict__ X, const float* __restrict__ gam,
    const float* __restrict__ bet, float* __restrict__ Y)
{
    const int row = blockIdx.x;
    const int tid = threadIdx.x;
    float4 v = *(const float4*)(X + (size_t)row * D_ + tid * 4);
    float s = v.x + v.y + v.z + v.w;
    float q = v.x * v.x + v.y * v.y + v.z * v.z + v.w * v.w;
    #pragma unroll
    for (int off = 16; off >= 1; off >>= 1) {
        s += __shfl_xor_sync(0xffffffffu, s, off);
        q += __shfl_xor_sync(0xffffffffu, q, off);
    }
    __shared__ float ss[8], sq[8];
    if ((tid & 31) == 0) { ss[tid >> 5] = s; sq[tid >> 5] = q; }
    __syncthreads();
    float ts = 0.f, tq = 0.f;
    #pragma unroll
    for (int i = 0; i < 8; i++) { ts += ss[i]; tq += sq[i]; }
    const float mu = ts * (1.0f / D_);
    const float var = tq * (1.0f / D_) - mu * mu;
    const float rstd = rsqrtf(var + 1e-5f);
    float4 g4 = *(const float4*)(gam + tid * 4);
    float4 b4 = *(const float4*)(bet + tid * 4);
    float4 y;
    y.x = (v.x - mu) * rstd * g4.x + b4.x;
    y.y = (v.y - mu) * rstd * g4.y + b4.y;
    y.z = (v.z - mu) * rstd * g4.z + b4.z;
    y.w = (v.w - mu) * rstd * g4.w + b4.w;
    *(float4*)(Y + (size_t)row * D_ + tid * 4) = y;
}

// ---------------------------------------------------------------------------
// Launch
// ---------------------------------------------------------------------------
extern "C" void kernel_launch(void* const* d_in, const int* in_sizes, int n_in,
                              void* d_out, int out_size)
{
    const float* x     = (const float*)d_in[0];
    const float* Wq    = (const float*)d_in[1];
    const float* Wk    = (const float*)d_in[2];
    const float* Wv    = (const float*)d_in[3];
    const float* Wo    = (const float*)d_in[4];
    const float* Wfc1  = (const float*)d_in[5];
    const float* Wfc2  = (const float*)d_in[6];
    const float* ln1g  = (const float*)d_in[7];
    const float* ln1b  = (const float*)d_in[8];
    const float* ln2g  = (const float*)d_in[9];
    const float* ln2b  = (const float*)d_in[10];
    float* out = (float*)d_out;

    float *q, *k, *v, *attn, *tmp, *h, *ff;
    cudaGetSymbolAddress((void**)&q,    g_q);
    cudaGetSymbolAddress((void**)&k,    g_k);
    cudaGetSymbolAddress((void**)&v,    g_v);
    cudaGetSymbolAddress((void**)&attn, g_attn);
    cudaGetSymbolAddress((void**)&tmp,  g_tmp);
    cudaGetSymbolAddress((void**)&h,    g_h);
    cudaGetSymbolAddress((void**)&ff,   g_ff);

    dim3 blk(256);
    dim3 gD(D_ / 128, M_ / 128);    // (8, 64)
    dim3 gF(FF_ / 128, M_ / 128);   // (32, 64)

    // QKV projections with head-scatter epilogue (TF32 tensor cores)
    tf32gemm_k<false, false, true><<<gD, blk>>>(x, Wq, nullptr, q, M_, D_, D_);
    tf32gemm_k<false, false, true><<<gD, blk>>>(x, Wk, nullptr, k, M_, D_, D_);
    tf32gemm_k<false, false, true><<<gD, blk>>>(x, Wv, nullptr, v, M_, D_, D_);

    // attention (TF32 tensor cores)
    flash_attn_mma_k<<<dim3(S_ / 64, B_ * H_), dim3(128)>>>(q, k, v, attn);

    // O projection + residual, LN1
    tf32gemm_k<false, true, false><<<gD, blk>>>(attn, Wo, x, tmp, M_, D_, D_);
    layernorm_k<<<M_, blk>>>(tmp, ln1g, ln1b, h);

    // FFN: fc1 (+ReLU), fc2 (+residual), LN2 -> out
    tf32gemm_k<true, false, false><<<gF, blk>>>(h, Wfc1, nullptr, ff, M_, FF_, D_);
    tf32gemm_k<false, true, false><<<gD, blk>>>(ff, Wfc2, h, tmp, M_, D_, FF_);
    layernorm_k<<<M_, blk>>>(tmp, ln2g, ln2b, out);
}

// round 8
// speedup vs baseline: 3.1095x; 1.0931x over previous
#include <cuda_runtime.h>
#include <cuda_bf16.h>
#include <cstdint>

// Problem constants
#define B_  4
#define S_  2048
#define D_  1024
#define H_  16
#define DK_ 64
#define FF_ 4096
#define M_  (B_ * S_)   // 8192

// ---------------------------------------------------------------------------
// Scratch (device globals; no allocation allowed)
// ---------------------------------------------------------------------------
__device__ float g_q[M_ * D_];
__device__ float g_k[M_ * D_];
__device__ float g_v[M_ * D_];
__device__ float g_attn[M_ * D_];
__device__ float g_tmp[M_ * D_];
__device__ float g_h[M_ * D_];
__device__ float g_ff[M_ * FF_];

__device__ __forceinline__ float to_tf32(float x) {
    float r;
    asm("cvt.rna.tf32.f32 %0, %1;" : "=f"(r) : "f"(x));
    return r;
}

__device__ __forceinline__ void mma_tf32(float* d, const float* a, const float* b) {
    asm volatile(
        "mma.sync.aligned.m16n8k8.row.col.f32.tf32.tf32.f32 "
        "{%0,%1,%2,%3}, {%4,%5,%6,%7}, {%8,%9}, {%0,%1,%2,%3};"
        : "+f"(d[0]), "+f"(d[1]), "+f"(d[2]), "+f"(d[3])
        : "r"(__float_as_uint(a[0])), "r"(__float_as_uint(a[1])),
          "r"(__float_as_uint(a[2])), "r"(__float_as_uint(a[3])),
          "r"(__float_as_uint(b[0])), "r"(__float_as_uint(b[1])));
}

#define CP16(dst, src) \
    asm volatile("cp.async.cg.shared.global [%0], [%1], 16;\n" :: "r"(dst), "l"(src))
#define CPCOMMIT() asm volatile("cp.async.commit_group;\n")
#define CPWAIT(n)  asm volatile("cp.async.wait_group %0;\n" :: "n"(n))

// ---------------------------------------------------------------------------
// TF32 GEMM body: C = A @ B (+res)(relu)(head-scatter)
// 128x128 tile, BK=32, 256 threads, 3-stage cp.async pipeline.
// Smem per stage: As[128][36] + Bs[32][136]; 3 stages = 107,520 B (dynamic).
// Inputs are raw fp32; tf32 mma truncates mantissa in hardware.
// ---------------------------------------------------------------------------
#define AST (128 * 36)
#define BST (32 * 136)
#define GEMM_SMEM_BYTES ((3 * (AST + BST)) * 4)

template <bool RELU, bool RESID, bool HEADOUT>
__device__ __forceinline__ void gemm_body(
    const float* __restrict__ A, const float* __restrict__ Bm,
    const float* __restrict__ Res, float* __restrict__ C,
    int M, int N, int K, float* smem)
{
    float* Asb = smem;
    float* Bsb = smem + 3 * AST;

    const int tid  = threadIdx.x;
    const int lane = tid & 31;
    const int wid  = tid >> 5;
    const int wm   = wid & 1;
    const int wn   = wid >> 1;
    const int gid  = lane >> 2;
    const int qid  = lane & 3;

    const int m0 = blockIdx.y * 128;
    const int n0 = blockIdx.x * 128;

    const int aRow = tid >> 1;
    const int aHalf = (tid & 1) * 16;
    const int bRow = tid >> 3;
    const int bCol = (tid & 7) * 16;

    const unsigned int aSm = (unsigned int)__cvta_generic_to_shared(Asb) + (aRow * 36 + aHalf) * 4;
    const unsigned int bSm = (unsigned int)__cvta_generic_to_shared(Bsb) + (bRow * 136 + bCol) * 4;
    const float* Ag = A + (size_t)(m0 + aRow) * K + aHalf;
    const float* Bg = Bm + (size_t)bRow * N + n0 + bCol;

    auto issue = [&](int t) {
        const int st = t % 3;
        const float* As_g = Ag + t * 32;
        const float* Bs_g = Bg + (size_t)t * 32 * N;
        const unsigned int ad = aSm + st * (AST * 4);
        const unsigned int bd = bSm + st * (BST * 4);
        #pragma unroll
        for (int i = 0; i < 4; i++) CP16(ad + i * 16, As_g + i * 4);
        #pragma unroll
        for (int i = 0; i < 4; i++) CP16(bd + i * 16, Bs_g + i * 4);
        CPCOMMIT();
    };

    float acc[4][4][4];
    #pragma unroll
    for (int i = 0; i < 4; i++)
        #pragma unroll
        for (int j = 0; j < 4; j++)
            #pragma unroll
            for (int r = 0; r < 4; r++) acc[i][j][r] = 0.f;

    const int nT = K / 32;
    issue(0);
    issue(1);

    for (int t = 0; t < nT; t++) {
        if (t + 1 < nT) { CPWAIT(1); } else { CPWAIT(0); }
        __syncthreads();           // tile t visible; all warps done with tile t-1
        if (t + 2 < nT) issue(t + 2);   // writes stage (t+2)%3 == (t-1)%3, now free

        const int stA = (t % 3) * AST;
        const int stB = (t % 3) * BST;
        #pragma unroll
        for (int ks = 0; ks < 4; ks++) {
            const int kb = ks * 8;
            float af[4][4], bf[4][2];
            #pragma unroll
            for (int mt = 0; mt < 4; mt++) {
                const int r = wm * 64 + mt * 16 + gid;
                af[mt][0] = Asb[stA + r * 36 + kb + qid];
                af[mt][1] = Asb[stA + (r + 8) * 36 + kb + qid];
                af[mt][2] = Asb[stA + r * 36 + kb + qid + 4];
                af[mt][3] = Asb[stA + (r + 8) * 36 + kb + qid + 4];
            }
            #pragma unroll
            for (int nt = 0; nt < 4; nt++) {
                const int c = wn * 32 + nt * 8 + gid;
                bf[nt][0] = Bsb[stB + (kb + qid) * 136 + c];
                bf[nt][1] = Bsb[stB + (kb + qid + 4) * 136 + c];
            }
            #pragma unroll
            for (int mt = 0; mt < 4; mt++)
                #pragma unroll
                for (int nt = 0; nt < 4; nt++)
                    mma_tf32(acc[mt][nt], af[mt], bf[nt]);
        }
    }

    #pragma unroll
    for (int mt = 0; mt < 4; mt++) {
        #pragma unroll
        for (int nt = 0; nt < 4; nt++) {
            const int rBase = m0 + wm * 64 + mt * 16 + gid;
            const int cBase = n0 + wn * 32 + nt * 8 + qid * 2;
            #pragma unroll
            for (int half = 0; half < 2; half++) {
                const int m = rBase + half * 8;
                float v0 = acc[mt][nt][half * 2 + 0];
                float v1 = acc[mt][nt][half * 2 + 1];
                if (RELU)  { v0 = fmaxf(v0, 0.f); v1 = fmaxf(v1, 0.f); }
                if (RESID) {
                    const float* rp = Res + (size_t)m * N + cBase;
                    v0 += rp[0]; v1 += rp[1];
                }
                if (HEADOUT) {
                    const int b = m >> 11, s = m & (S_ - 1);
                    const int h = cBase >> 6, d = cBase & (DK_ - 1);
                    float* dst = C + ((size_t)(b * H_ + h) * S_ + s) * DK_ + d;
                    dst[0] = v0; dst[1] = v1;
                } else {
                    float* dst = C + (size_t)m * N + cBase;
                    dst[0] = v0; dst[1] = v1;
                }
            }
        }
    }
}

// Fused QKV: blockIdx.z selects weight/output
__global__ __launch_bounds__(256) void qkv_gemm_k(
    const float* __restrict__ x,
    const float* __restrict__ Wq, const float* __restrict__ Wk,
    const float* __restrict__ Wv,
    float* __restrict__ q, float* __restrict__ k, float* __restrict__ v)
{
    extern __shared__ float smem[];
    const float* W = (blockIdx.z == 0) ? Wq : (blockIdx.z == 1) ? Wk : Wv;
    float* C = (blockIdx.z == 0) ? q : (blockIdx.z == 1) ? k : v;
    gemm_body<false, false, true>(x, W, nullptr, C, M_, D_, D_, smem);
}

template <bool RELU, bool RESID>
__global__ __launch_bounds__(256) void tf32gemm_k(
    const float* __restrict__ A, const float* __restrict__ Bm,
    const float* __restrict__ Res, float* __restrict__ C,
    int M, int N, int K)
{
    extern __shared__ float smem[];
    gemm_body<RELU, RESID, false>(A, Bm, Res, C, M, N, K, smem);
}

// ---------------------------------------------------------------------------
// TF32 mma flash attention. One block per (bh, q-tile of 64).
// 128 threads = 4 warps; warp w owns q rows [w*16, w*16+16).
// Q fragments live in registers (loaded once, reused over all 64 key tiles).
// ---------------------------------------------------------------------------
__global__ __launch_bounds__(128) void flash_attn_mma_k(
    const float* __restrict__ Q, const float* __restrict__ K,
    const float* __restrict__ V, float* __restrict__ O)
{
    __shared__ float Qs[64][68];   // staging only (read once into regs)
    __shared__ float Ks[32][68];   // [key][d] banks: 4*gid+qid
    __shared__ float Vs[32][72];   // [key][d] banks: 8*qid+gid
    __shared__ float Ps[64][36];   // [q][key] banks: 4*gid+qid

    const int tid  = threadIdx.x;
    const int lane = tid & 31;
    const int wid  = tid >> 5;
    const int gid  = lane >> 2;
    const int qid  = lane & 3;
    const int wq0  = wid * 16;

    const int qt = blockIdx.x;
    const int bh = blockIdx.y;

    const float* Qb = Q + ((size_t)bh * S_ + qt * 64) * DK_;
    const float* Kb = K + (size_t)bh * S_ * DK_;
    const float* Vb = V + (size_t)bh * S_ * DK_;

    #pragma unroll
    for (int i = 0; i < 8; i++) {
        int idx = tid + i * 128;
        int r = idx >> 4, f = (idx & 15) << 2;
        float4 v = *(const float4*)(Qb + r * DK_ + f);
        float4 t;
        t.x = to_tf32(v.x * 0.125f); t.y = to_tf32(v.y * 0.125f);
        t.z = to_tf32(v.z * 0.125f); t.w = to_tf32(v.w * 0.125f);
        *(float4*)&Qs[r][f] = t;
    }
    __syncthreads();

    // Q fragments -> registers (A-frag for all 8 k-steps)
    float qf[8][4];
    #pragma unroll
    for (int ks = 0; ks < 8; ks++) {
        const int kb = ks * 8;
        qf[ks][0] = Qs[wq0 + gid][kb + qid];
        qf[ks][1] = Qs[wq0 + gid + 8][kb + qid];
        qf[ks][2] = Qs[wq0 + gid][kb + qid + 4];
        qf[ks][3] = Qs[wq0 + gid + 8][kb + qid + 4];
    }

    float oacc[8][4];
    #pragma unroll
    for (int nt = 0; nt < 8; nt++)
        #pragma unroll
        for (int r = 0; r < 4; r++) oacc[nt][r] = 0.f;
    float mrow[2] = {-1e30f, -1e30f};
    float lrow[2] = {0.f, 0.f};

    for (int kt = 0; kt < S_ / 32; kt++) {
        __syncthreads();
        const float* Kp = Kb + (size_t)kt * 32 * DK_;
        const float* Vp = Vb + (size_t)kt * 32 * DK_;
        #pragma unroll
        for (int i = 0; i < 4; i++) {
            int idx = tid + i * 128;
            int r = idx >> 4, f = (idx & 15) << 2;
            float4 kv = *(const float4*)(Kp + r * DK_ + f);
            float4 tk;
            tk.x = to_tf32(kv.x); tk.y = to_tf32(kv.y);
            tk.z = to_tf32(kv.z); tk.w = to_tf32(kv.w);
            *(float4*)&Ks[r][f] = tk;
            float4 vv = *(const float4*)(Vp + r * DK_ + f);
            float4 tv;
            tv.x = to_tf32(vv.x); tv.y = to_tf32(vv.y);
            tv.z = to_tf32(vv.z); tv.w = to_tf32(vv.w);
            *(float4*)&Vs[r][f] = tv;
        }
        __syncthreads();

        // S = Q K^T : 16 q x 32 keys, k = 64
        float sacc[4][4];
        #pragma unroll
        for (int nt = 0; nt < 4; nt++)
            #pragma unroll
            for (int r = 0; r < 4; r++) sacc[nt][r] = 0.f;

        #pragma unroll
        for (int ks = 0; ks < 8; ks++) {
            const int kb = ks * 8;
            #pragma unroll
            for (int nt = 0; nt < 4; nt++) {
                float bf[2];
                bf[0] = Ks[nt * 8 + gid][kb + qid];
                bf[1] = Ks[nt * 8 + gid][kb + qid + 4];
                mma_tf32(sacc[nt], qf[ks], bf);
            }
        }

        // online softmax
        #pragma unroll
        for (int i = 0; i < 2; i++) {
            const int b0 = i * 2;
            float tm = -1e30f;
            #pragma unroll
            for (int nt = 0; nt < 4; nt++)
                tm = fmaxf(tm, fmaxf(sacc[nt][b0], sacc[nt][b0 + 1]));
            tm = fmaxf(tm, __shfl_xor_sync(0xffffffffu, tm, 1));
            tm = fmaxf(tm, __shfl_xor_sync(0xffffffffu, tm, 2));
            float nm = fmaxf(mrow[i], tm);
            float fac = __expf(mrow[i] - nm);
            mrow[i] = nm;
            float rs = 0.f;
            #pragma unroll
            for (int nt = 0; nt < 4; nt++) {
                float p0 = __expf(sacc[nt][b0] - nm);
                float p1 = __expf(sacc[nt][b0 + 1] - nm);
                sacc[nt][b0] = p0; sacc[nt][b0 + 1] = p1;
                rs += p0 + p1;
            }
            rs += __shfl_xor_sync(0xffffffffu, rs, 1);
            rs += __shfl_xor_sync(0xffffffffu, rs, 2);
            lrow[i] = lrow[i] * fac + rs;
            #pragma unroll
            for (int nt = 0; nt < 8; nt++) {
                oacc[nt][b0] *= fac;
                oacc[nt][b0 + 1] *= fac;
            }
        }

        // write P slab (own warp rows only)
        #pragma unroll
        for (int nt = 0; nt < 4; nt++) {
            *(float2*)&Ps[wq0 + gid][nt * 8 + qid * 2] =
                make_float2(to_tf32(sacc[nt][0]), to_tf32(sacc[nt][1]));
            *(float2*)&Ps[wq0 + gid + 8][nt * 8 + qid * 2] =
                make_float2(to_tf32(sacc[nt][2]), to_tf32(sacc[nt][3]));
        }
        __syncwarp();

        // O += P V : 16 q x 64 d, k = 32 keys
        #pragma unroll
        for (int ks = 0; ks < 4; ks++) {
            const int kb = ks * 8;
            float af[4];
            af[0] = Ps[wq0 + gid][kb + qid];
            af[1] = Ps[wq0 + gid + 8][kb + qid];
            af[2] = Ps[wq0 + gid][kb + qid + 4];
            af[3] = Ps[wq0 + gid + 8][kb + qid + 4];
            #pragma unroll
            for (int nt = 0; nt < 8; nt++) {
                float bf[2];
                bf[0] = Vs[kb + qid][nt * 8 + gid];
                bf[1] = Vs[kb + qid + 4][nt * 8 + gid];
                mma_tf32(oacc[nt], af, bf);
            }
        }
    }

    const int b = bh >> 4, h = bh & 15;
    #pragma unroll
    for (int i = 0; i < 2; i++) {
        float inv = 1.0f / lrow[i];
        int row = b * S_ + qt * 64 + wq0 + gid + i * 8;
        float* dst = O + (size_t)row * D_ + h * DK_;
        #pragma unroll
        for (int nt = 0; nt < 8; nt++) {
            *(float2*)&dst[nt * 8 + qid * 2] =
                make_float2(oacc[nt][i * 2] * inv, oacc[nt][i * 2 + 1] * inv);
        }
    }
}

// ---------------------------------------------------------------------------
// LayerNorm: one block (256 threads) per row of 1024
// ---------------------------------------------------------------------------
__global__ __launch_bounds__(256) void layernorm_k(
    const float* __restrict__ X, const float* __restrict__ gam,
    const float* __restrict__ bet, float* __restrict__ Y)
{
    const int row = blockIdx.x;
    const int tid = threadIdx.x;
    float4 v = *(const float4*)(X + (size_t)row * D_ + tid * 4);
    float s = v.x + v.y + v.z + v.w;
    float q = v.x * v.x + v.y * v.y + v.z * v.z + v.w * v.w;
    #pragma unroll
    for (int off = 16; off >= 1; off >>= 1) {
        s += __shfl_xor_sync(0xffffffffu, s, off);
        q += __shfl_xor_sync(0xffffffffu, q, off);
    }
    __shared__ float ss[8], sq[8];
    if ((tid & 31) == 0) { ss[tid >> 5] = s; sq[tid >> 5] = q; }
    __syncthreads();
    float ts = 0.f, tq = 0.f;
    #pragma unroll
    for (int i = 0; i < 8; i++) { ts += ss[i]; tq += sq[i]; }
    const float mu = ts * (1.0f / D_);
    const float var = tq * (1.0f / D_) - mu * mu;
    const float rstd = rsqrtf(var + 1e-5f);
    float4 g4 = *(const float4*)(gam + tid * 4);
    float4 b4 = *(const float4*)(bet + tid * 4);
    float4 y;
    y.x = (v.x - mu) * rstd * g4.x + b4.x;
    y.y = (v.y - mu) * rstd * g4.y + b4.y;
    y.z = (v.z - mu) * rstd * g4.z + b4.z;
    y.w = (v.w - mu) * rstd * g4.w + b4.w;
    *(float4*)(Y + (size_t)row * D_ + tid * 4) = y;
}

// ---------------------------------------------------------------------------
// Launch
// ---------------------------------------------------------------------------
extern "C" void kernel_launch(void* const* d_in, const int* in_sizes, int n_in,
                              void* d_out, int out_size)
{
    const float* x     = (const float*)d_in[0];
    const float* Wq    = (const float*)d_in[1];
    const float* Wk    = (const float*)d_in[2];
    const float* Wv    = (const float*)d_in[3];
    const float* Wo    = (const float*)d_in[4];
    const float* Wfc1  = (const float*)d_in[5];
    const float* Wfc2  = (const float*)d_in[6];
    const float* ln1g  = (const float*)d_in[7];
    const float* ln1b  = (const float*)d_in[8];
    const float* ln2g  = (const float*)d_in[9];
    const float* ln2b  = (const float*)d_in[10];
    float* out = (float*)d_out;

    float *q, *k, *v, *attn, *tmp, *h, *ff;
    cudaGetSymbolAddress((void**)&q,    g_q);
    cudaGetSymbolAddress((void**)&k,    g_k);
    cudaGetSymbolAddress((void**)&v,    g_v);
    cudaGetSymbolAddress((void**)&attn, g_attn);
    cudaGetSymbolAddress((void**)&tmp,  g_tmp);
    cudaGetSymbolAddress((void**)&h,    g_h);
    cudaGetSymbolAddress((void**)&ff,   g_ff);

    cudaFuncSetAttribute(qkv_gemm_k,
        cudaFuncAttributeMaxDynamicSharedMemorySize, GEMM_SMEM_BYTES);
    cudaFuncSetAttribute(tf32gemm_k<false, true>,
        cudaFuncAttributeMaxDynamicSharedMemorySize, GEMM_SMEM_BYTES);
    cudaFuncSetAttribute(tf32gemm_k<true, false>,
        cudaFuncAttributeMaxDynamicSharedMemorySize, GEMM_SMEM_BYTES);

    dim3 blk(256);
    dim3 gQKV(D_ / 128, M_ / 128, 3);   // (8, 64, 3)
    dim3 gD(D_ / 128, M_ / 128);        // (8, 64)
    dim3 gF(FF_ / 128, M_ / 128);       // (32, 64)

    // fused QKV projections (head-scatter epilogue)
    qkv_gemm_k<<<gQKV, blk, GEMM_SMEM_BYTES>>>(x, Wq, Wk, Wv, q, k, v);

    // attention (TF32 tensor cores)
    flash_attn_mma_k<<<dim3(S_ / 64, B_ * H_), dim3(128)>>>(q, k, v, attn);

    // O projection + residual, LN1
    tf32gemm_k<false, true><<<gD, blk, GEMM_SMEM_BYTES>>>(attn, Wo, x, tmp, M_, D_, D_);
    layernorm_k<<<M_, blk>>>(tmp, ln1g, ln1b, h);

    // FFN: fc1 (+ReLU), fc2 (+residual), LN2 -> out
    tf32gemm_k<true, false><<<gF, blk, GEMM_SMEM_BYTES>>>(h, Wfc1, nullptr, ff, M_, FF_, D_);
    tf32gemm_k<false, true><<<gD, blk, GEMM_SMEM_BYTES>>>(ff, Wfc2, h, tmp, M_, D_, FF_);
    layernorm_k<<<M_, blk>>>(tmp, ln2g, ln2b, out);
}

// round 9
// speedup vs baseline: 4.3158x; 1.3879x over previous
#include <cuda_runtime.h>
#include <cuda_bf16.h>
#include <cstdint>

// Problem constants
#define B_  4
#define S_  2048
#define D_  1024
#define H_  16
#define DK_ 64
#define FF_ 4096
#define M_  (B_ * S_)   // 8192

// ---------------------------------------------------------------------------
// Scratch (device globals; no allocation allowed)
// ---------------------------------------------------------------------------
__device__ float g_q[M_ * D_];       // rounded + 0.125-scaled
__device__ float g_k[M_ * D_];       // rounded
__device__ float g_v[M_ * D_];       // rounded
__device__ float g_attn[M_ * D_];    // rounded (A of O-proj)
__device__ float g_tmp[M_ * D_];
__device__ float g_h[M_ * D_];       // fp32 (residual for fc2)
__device__ float g_hr[M_ * D_];      // rounded (A of fc1)
__device__ float g_ff[M_ * FF_];     // rounded (A of fc2)
__device__ float g_xr[M_ * D_];      // rounded x
__device__ float g_wq[D_ * D_];
__device__ float g_wk[D_ * D_];
__device__ float g_wv[D_ * D_];
__device__ float g_wo[D_ * D_];
__device__ float g_w1[D_ * FF_];
__device__ float g_w2[FF_ * D_];

__device__ __forceinline__ float to_tf32(float x) {
    float r;
    asm("cvt.rna.tf32.f32 %0, %1;" : "=f"(r) : "f"(x));
    return r;
}

__device__ __forceinline__ void mma_tf32(float* d, const float* a, const float* b) {
    asm volatile(
        "mma.sync.aligned.m16n8k8.row.col.f32.tf32.tf32.f32 "
        "{%0,%1,%2,%3}, {%4,%5,%6,%7}, {%8,%9}, {%0,%1,%2,%3};"
        : "+f"(d[0]), "+f"(d[1]), "+f"(d[2]), "+f"(d[3])
        : "r"(__float_as_uint(a[0])), "r"(__float_as_uint(a[1])),
          "r"(__float_as_uint(a[2])), "r"(__float_as_uint(a[3])),
          "r"(__float_as_uint(b[0])), "r"(__float_as_uint(b[1])));
}

#define CP16(dst, src) \
    asm volatile("cp.async.cg.shared.global [%0], [%1], 16;\n" :: "r"(dst), "l"(src))
#define CPCOMMIT() asm volatile("cp.async.commit_group;\n")
#define CPWAIT(n)  asm volatile("cp.async.wait_group %0;\n" :: "n"(n))

// ---------------------------------------------------------------------------
// Pre-round: y = tf32_round(x), vectorized
// ---------------------------------------------------------------------------
__global__ __launch_bounds__(256) void roundcopy_k(
    const float* __restrict__ X, float* __restrict__ Y, int n4)
{
    int i = blockIdx.x * 256 + threadIdx.x;
    if (i < n4) {
        float4 v = ((const float4*)X)[i];
        float4 t;
        t.x = to_tf32(v.x); t.y = to_tf32(v.y);
        t.z = to_tf32(v.z); t.w = to_tf32(v.w);
        ((float4*)Y)[i] = t;
    }
}

// ---------------------------------------------------------------------------
// TF32 GEMM: 128x128 CTA tile, BK=32, 128 threads (4 warps), warp tile 64x64.
// 3-stage cp.async pipeline. Operands must be pre-rounded tf32 values.
// ---------------------------------------------------------------------------
#define AST (128 * 36)
#define BST (32 * 136)
#define GEMM_SMEM_BYTES ((3 * (AST + BST)) * 4)

template <bool RELU, bool RESID, bool HEADOUT, bool ROUND>
__device__ __forceinline__ void gemm_body(
    const float* __restrict__ A, const float* __restrict__ Bm,
    const float* __restrict__ Res, float* __restrict__ C,
    int M, int N, int K, float* smem, float outScale)
{
    float* Asb = smem;
    float* Bsb = smem + 3 * AST;

    const int tid  = threadIdx.x;
    const int lane = tid & 31;
    const int wid  = tid >> 5;        // 0..3
    const int wm   = wid & 1;         // 64-row half
    const int wn   = wid >> 1;        // 64-col half
    const int gid  = lane >> 2;       // 0..7
    const int qid  = lane & 3;        // 0..3

    const int m0 = blockIdx.y * 128;
    const int n0 = blockIdx.x * 128;

    // loaders: A rows aRow0+16i (i<8), col aCol..aCol+3 ; B rows bRow0+4i, col bCol..bCol+3
    const int aRow0 = tid >> 3;           // 0..15
    const int aCol  = (tid & 7) * 4;      // 0..28
    const int bRow0 = tid >> 5;           // 0..3
    const int bCol  = (tid & 31) * 4;     // 0..124

    const unsigned int aSm = (unsigned int)__cvta_generic_to_shared(Asb) + (aRow0 * 36 + aCol) * 4;
    const unsigned int bSm = (unsigned int)__cvta_generic_to_shared(Bsb) + (bRow0 * 136 + bCol) * 4;
    const float* Ag = A + (size_t)(m0 + aRow0) * K + aCol;
    const float* Bg = Bm + (size_t)bRow0 * N + n0 + bCol;

    auto issue = [&](int t) {
        const int st = t % 3;
        const unsigned int ad = aSm + st * (AST * 4);
        const unsigned int bd = bSm + st * (BST * 4);
        const float* As_g = Ag + t * 32;
        const float* Bs_g = Bg + (size_t)(t * 32) * N;
        #pragma unroll
        for (int i = 0; i < 8; i++)
            CP16(ad + i * (16 * 36 * 4), As_g + (size_t)(16 * i) * K);
        #pragma unroll
        for (int i = 0; i < 8; i++)
            CP16(bd + i * (4 * 136 * 4), Bs_g + (size_t)(4 * i) * N);
        CPCOMMIT();
    };

    float acc[4][8][4];
    #pragma unroll
    for (int i = 0; i < 4; i++)
        #pragma unroll
        for (int j = 0; j < 8; j++)
            #pragma unroll
            for (int r = 0; r < 4; r++) acc[i][j][r] = 0.f;

    const int nT = K / 32;
    issue(0);
    issue(1);

    for (int t = 0; t < nT; t++) {
        if (t + 1 < nT) { CPWAIT(1); } else { CPWAIT(0); }
        __syncthreads();
        if (t + 2 < nT) issue(t + 2);

        const int stA = (t % 3) * AST;
        const int stB = (t % 3) * BST;
        #pragma unroll
        for (int ks = 0; ks < 4; ks++) {
            const int kb = ks * 8;
            float af[4][4], bf[8][2];
            #pragma unroll
            for (int mt = 0; mt < 4; mt++) {
                const int r = wm * 64 + mt * 16 + gid;
                af[mt][0] = Asb[stA + r * 36 + kb + qid];
                af[mt][1] = Asb[stA + (r + 8) * 36 + kb + qid];
                af[mt][2] = Asb[stA + r * 36 + kb + qid + 4];
                af[mt][3] = Asb[stA + (r + 8) * 36 + kb + qid + 4];
            }
            #pragma unroll
            for (int nt = 0; nt < 8; nt++) {
                const int c = wn * 64 + nt * 8 + gid;
                bf[nt][0] = Bsb[stB + (kb + qid) * 136 + c];
                bf[nt][1] = Bsb[stB + (kb + qid + 4) * 136 + c];
            }
            #pragma unroll
            for (int mt = 0; mt < 4; mt++)
                #pragma unroll
                for (int nt = 0; nt < 8; nt++)
                    mma_tf32(acc[mt][nt], af[mt], bf[nt]);
        }
    }

    #pragma unroll
    for (int mt = 0; mt < 4; mt++) {
        #pragma unroll
        for (int nt = 0; nt < 8; nt++) {
            const int rBase = m0 + wm * 64 + mt * 16 + gid;
            const int cBase = n0 + wn * 64 + nt * 8 + qid * 2;
            #pragma unroll
            for (int half = 0; half < 2; half++) {
                const int m = rBase + half * 8;
                float v0 = acc[mt][nt][half * 2 + 0];
                float v1 = acc[mt][nt][half * 2 + 1];
                if (RELU)  { v0 = fmaxf(v0, 0.f); v1 = fmaxf(v1, 0.f); }
                if (RESID) {
                    const float* rp = Res + (size_t)m * N + cBase;
                    v0 += rp[0]; v1 += rp[1];
                }
                if (ROUND) {
                    v0 = to_tf32(v0 * outScale);
                    v1 = to_tf32(v1 * outScale);
                }
                if (HEADOUT) {
                    const int b = m >> 11, s = m & (S_ - 1);
                    const int h = cBase >> 6, d = cBase & (DK_ - 1);
                    float* dst = C + ((size_t)(b * H_ + h) * S_ + s) * DK_ + d;
                    dst[0] = v0; dst[1] = v1;
                } else {
                    float* dst = C + (size_t)m * N + cBase;
                    dst[0] = v0; dst[1] = v1;
                }
            }
        }
    }
}

// Fused QKV: blockIdx.z selects weight/output. Output rounded; q scaled by 0.125.
__global__ __launch_bounds__(128) void qkv_gemm_k(
    const float* __restrict__ x,
    const float* __restrict__ Wq, const float* __restrict__ Wk,
    const float* __restrict__ Wv,
    float* __restrict__ q, float* __restrict__ k, float* __restrict__ v)
{
    extern __shared__ float smem[];
    const float* W = (blockIdx.z == 0) ? Wq : (blockIdx.z == 1) ? Wk : Wv;
    float* C = (blockIdx.z == 0) ? q : (blockIdx.z == 1) ? k : v;
    const float sc = (blockIdx.z == 0) ? 0.125f : 1.0f;
    gemm_body<false, false, true, true>(x, W, nullptr, C, M_, D_, D_, smem, sc);
}

template <bool RELU, bool RESID, bool ROUND>
__global__ __launch_bounds__(128) void tf32gemm_k(
    const float* __restrict__ A, const float* __restrict__ Bm,
    const float* __restrict__ Res, float* __restrict__ C,
    int M, int N, int K)
{
    extern __shared__ float smem[];
    gemm_body<RELU, RESID, false, ROUND>(A, Bm, Res, C, M, N, K, smem, 1.0f);
}

// ---------------------------------------------------------------------------
// TF32 mma flash attention. Inputs pre-rounded (q pre-scaled).
// One block per (bh, q-tile of 64); 128 threads = 4 warps.
// ---------------------------------------------------------------------------
__global__ __launch_bounds__(128) void flash_attn_mma_k(
    const float* __restrict__ Q, const float* __restrict__ K,
    const float* __restrict__ V, float* __restrict__ O)
{
    __shared__ float Qs[64][68];
    __shared__ float Ks[32][68];
    __shared__ float Vs[32][72];
    __shared__ float Ps[64][36];

    const int tid  = threadIdx.x;
    const int lane = tid & 31;
    const int wid  = tid >> 5;
    const int gid  = lane >> 2;
    const int qid  = lane & 3;
    const int wq0  = wid * 16;

    const int qt = blockIdx.x;
    const int bh = blockIdx.y;

    const float* Qb = Q + ((size_t)bh * S_ + qt * 64) * DK_;
    const float* Kb = K + (size_t)bh * S_ * DK_;
    const float* Vb = V + (size_t)bh * S_ * DK_;

    #pragma unroll
    for (int i = 0; i < 8; i++) {
        int idx = tid + i * 128;
        int r = idx >> 4, f = (idx & 15) << 2;
        *(float4*)&Qs[r][f] = *(const float4*)(Qb + r * DK_ + f);
    }
    __syncthreads();

    float qf[8][4];
    #pragma unroll
    for (int ks = 0; ks < 8; ks++) {
        const int kb = ks * 8;
        qf[ks][0] = Qs[wq0 + gid][kb + qid];
        qf[ks][1] = Qs[wq0 + gid + 8][kb + qid];
        qf[ks][2] = Qs[wq0 + gid][kb + qid + 4];
        qf[ks][3] = Qs[wq0 + gid + 8][kb + qid + 4];
    }

    float oacc[8][4];
    #pragma unroll
    for (int nt = 0; nt < 8; nt++)
        #pragma unroll
        for (int r = 0; r < 4; r++) oacc[nt][r] = 0.f;
    float mrow[2] = {-1e30f, -1e30f};
    float lrow[2] = {0.f, 0.f};

    for (int kt = 0; kt < S_ / 32; kt++) {
        __syncthreads();
        const float* Kp = Kb + (size_t)kt * 32 * DK_;
        const float* Vp = Vb + (size_t)kt * 32 * DK_;
        #pragma unroll
        for (int i = 0; i < 4; i++) {
            int idx = tid + i * 128;
            int r = idx >> 4, f = (idx & 15) << 2;
            *(float4*)&Ks[r][f] = *(const float4*)(Kp + r * DK_ + f);
            *(float4*)&Vs[r][f] = *(const float4*)(Vp + r * DK_ + f);
        }
        __syncthreads();

        float sacc[4][4];
        #pragma unroll
        for (int nt = 0; nt < 4; nt++)
            #pragma unroll
            for (int r = 0; r < 4; r++) sacc[nt][r] = 0.f;

        #pragma unroll
        for (int ks = 0; ks < 8; ks++) {
            const int kb = ks * 8;
            #pragma unroll
            for (int nt = 0; nt < 4; nt++) {
                float bf[2];
                bf[0] = Ks[nt * 8 + gid][kb + qid];
                bf[1] = Ks[nt * 8 + gid][kb + qid + 4];
                mma_tf32(sacc[nt], qf[ks], bf);
            }
        }

        #pragma unroll
        for (int i = 0; i < 2; i++) {
            const int b0 = i * 2;
            float tm = -1e30f;
            #pragma unroll
            for (int nt = 0; nt < 4; nt++)
                tm = fmaxf(tm, fmaxf(sacc[nt][b0], sacc[nt][b0 + 1]));
            tm = fmaxf(tm, __shfl_xor_sync(0xffffffffu, tm, 1));
            tm = fmaxf(tm, __shfl_xor_sync(0xffffffffu, tm, 2));
            float nm = fmaxf(mrow[i], tm);
            float fac = __expf(mrow[i] - nm);
            mrow[i] = nm;
            float rs = 0.f;
            #pragma unroll
            for (int nt = 0; nt < 4; nt++) {
                float p0 = __expf(sacc[nt][b0] - nm);
                float p1 = __expf(sacc[nt][b0 + 1] - nm);
                sacc[nt][b0] = p0; sacc[nt][b0 + 1] = p1;
                rs += p0 + p1;
            }
            rs += __shfl_xor_sync(0xffffffffu, rs, 1);
            rs += __shfl_xor_sync(0xffffffffu, rs, 2);
            lrow[i] = lrow[i] * fac + rs;
            #pragma unroll
            for (int nt = 0; nt < 8; nt++) {
                oacc[nt][b0] *= fac;
                oacc[nt][b0 + 1] *= fac;
            }
        }

        #pragma unroll
        for (int nt = 0; nt < 4; nt++) {
            *(float2*)&Ps[wq0 + gid][nt * 8 + qid * 2] =
                make_float2(to_tf32(sacc[nt][0]), to_tf32(sacc[nt][1]));
            *(float2*)&Ps[wq0 + gid + 8][nt * 8 + qid * 2] =
                make_float2(to_tf32(sacc[nt][2]), to_tf32(sacc[nt][3]));
        }
        __syncwarp();

        #pragma unroll
        for (int ks = 0; ks < 4; ks++) {
            const int kb = ks * 8;
            float af[4];
            af[0] = Ps[wq0 + gid][kb + qid];
            af[1] = Ps[wq0 + gid + 8][kb + qid];
            af[2] = Ps[wq0 + gid][kb + qid + 4];
            af[3] = Ps[wq0 + gid + 8][kb + qid + 4];
            #pragma unroll
            for (int nt = 0; nt < 8; nt++) {
                float bf[2];
                bf[0] = Vs[kb + qid][nt * 8 + gid];
                bf[1] = Vs[kb + qid + 4][nt * 8 + gid];
                mma_tf32(oacc[nt], af, bf);
            }
        }
    }

    // epilogue: normalize, round (A-operand of O-proj), scatter
    const int b = bh >> 4, h = bh & 15;
    #pragma unroll
    for (int i = 0; i < 2; i++) {
        float inv = 1.0f / lrow[i];
        int row = b * S_ + qt * 64 + wq0 + gid + i * 8;
        float* dst = O + (size_t)row * D_ + h * DK_;
        #pragma unroll
        for (int nt = 0; nt < 8; nt++) {
            *(float2*)&dst[nt * 8 + qid * 2] =
                make_float2(to_tf32(oacc[nt][i * 2] * inv),
                            to_tf32(oacc[nt][i * 2 + 1] * inv));
        }
    }
}

// ---------------------------------------------------------------------------
// LayerNorm: one block (256 threads) per row of 1024.
// Optionally writes a tf32-rounded second copy (A-operand for next GEMM).
// ---------------------------------------------------------------------------
__global__ __launch_bounds__(256) void layernorm_k(
    const float* __restrict__ X, const float* __restrict__ gam,
    const float* __restrict__ bet, float* __restrict__ Y,
    float* __restrict__ Yr)
{
    const int row = blockIdx.x;
    const int tid = threadIdx.x;
    float4 v = *(const float4*)(X + (size_t)row * D_ + tid * 4);
    float s = v.x + v.y + v.z + v.w;
    float q = v.x * v.x + v.y * v.y + v.z * v.z + v.w * v.w;
    #pragma unroll
    for (int off = 16; off >= 1; off >>= 1) {
        s += __shfl_xor_sync(0xffffffffu, s, off);
        q += __shfl_xor_sync(0xffffffffu, q, off);
    }
    __shared__ float ss[8], sq[8];
    if ((tid & 31) == 0) { ss[tid >> 5] = s; sq[tid >> 5] = q; }
    __syncthreads();
    float ts = 0.f, tq = 0.f;
    #pragma unroll
    for (int i = 0; i < 8; i++) { ts += ss[i]; tq += sq[i]; }
    const float mu = ts * (1.0f / D_);
    const float var = tq * (1.0f / D_) - mu * mu;
    const float rstd = rsqrtf(var + 1e-5f);
    float4 g4 = *(const float4*)(gam + tid * 4);
    float4 b4 = *(const float4*)(bet + tid * 4);
    float4 y;
    y.x = (v.x - mu) * rstd * g4.x + b4.x;
    y.y = (v.y - mu) * rstd * g4.y + b4.y;
    y.z = (v.z - mu) * rstd * g4.z + b4.z;
    y.w = (v.w - mu) * rstd * g4.w + b4.w;
    *(float4*)(Y + (size_t)row * D_ + tid * 4) = y;
    if (Yr) {
        float4 r;
        r.x = to_tf32(y.x); r.y = to_tf32(y.y);
        r.z = to_tf32(y.z); r.w = to_tf32(y.w);
        *(float4*)(Yr + (size_t)row * D_ + tid * 4) = r;
    }
}

// ---------------------------------------------------------------------------
// Launch
// ---------------------------------------------------------------------------
extern "C" void kernel_launch(void* const* d_in, const int* in_sizes, int n_in,
                              void* d_out, int out_size)
{
    const float* x     = (const float*)d_in[0];
    const float* Wq    = (const float*)d_in[1];
    const float* Wk    = (const float*)d_in[2];
    const float* Wv    = (const float*)d_in[3];
    const float* Wo    = (const float*)d_in[4];
    const float* Wfc1  = (const float*)d_in[5];
    const float* Wfc2  = (const float*)d_in[6];
    const float* ln1g  = (const float*)d_in[7];
    const float* ln1b  = (const float*)d_in[8];
    const float* ln2g  = (const float*)d_in[9];
    const float* ln2b  = (const float*)d_in[10];
    float* out = (float*)d_out;

    float *q, *k, *v, *attn, *tmp, *h, *hr, *ff;
    float *xr, *wq, *wk, *wv, *wo, *w1, *w2;
    cudaGetSymbolAddress((void**)&q,    g_q);
    cudaGetSymbolAddress((void**)&k,    g_k);
    cudaGetSymbolAddress((void**)&v,    g_v);
    cudaGetSymbolAddress((void**)&attn, g_attn);
    cudaGetSymbolAddress((void**)&tmp,  g_tmp);
    cudaGetSymbolAddress((void**)&h,    g_h);
    cudaGetSymbolAddress((void**)&hr,   g_hr);
    cudaGetSymbolAddress((void**)&ff,   g_ff);
    cudaGetSymbolAddress((void**)&xr,   g_xr);
    cudaGetSymbolAddress((void**)&wq,   g_wq);
    cudaGetSymbolAddress((void**)&wk,   g_wk);
    cudaGetSymbolAddress((void**)&wv,   g_wv);
    cudaGetSymbolAddress((void**)&wo,   g_wo);
    cudaGetSymbolAddress((void**)&w1,   g_w1);
    cudaGetSymbolAddress((void**)&w2,   g_w2);

    cudaFuncSetAttribute(qkv_gemm_k,
        cudaFuncAttributeMaxDynamicSharedMemorySize, GEMM_SMEM_BYTES);
    cudaFuncSetAttribute(tf32gemm_k<false, true, false>,
        cudaFuncAttributeMaxDynamicSharedMemorySize, GEMM_SMEM_BYTES);
    cudaFuncSetAttribute(tf32gemm_k<true, false, true>,
        cudaFuncAttributeMaxDynamicSharedMemorySize, GEMM_SMEM_BYTES);

    dim3 blk(128);
    dim3 gQKV(D_ / 128, M_ / 128, 3);   // (8, 64, 3)
    dim3 gD(D_ / 128, M_ / 128);        // (8, 64)
    dim3 gF(FF_ / 128, M_ / 128);       // (32, 64)

    // pre-round x and weights to tf32 (cp.async path then truncates exactly)
    roundcopy_k<<<(M_ * D_ / 4 + 255) / 256, 256>>>(x,    xr, M_ * D_ / 4);
    roundcopy_k<<<(D_ * D_ / 4 + 255) / 256, 256>>>(Wq,   wq, D_ * D_ / 4);
    roundcopy_k<<<(D_ * D_ / 4 + 255) / 256, 256>>>(Wk,   wk, D_ * D_ / 4);
    roundcopy_k<<<(D_ * D_ / 4 + 255) / 256, 256>>>(Wv,   wv, D_ * D_ / 4);
    roundcopy_k<<<(D_ * D_ / 4 + 255) / 256, 256>>>(Wo,   wo, D_ * D_ / 4);
    roundcopy_k<<<(D_ * FF_ / 4 + 255) / 256, 256>>>(Wfc1, w1, D_ * FF_ / 4);
    roundcopy_k<<<(FF_ * D_ / 4 + 255) / 256, 256>>>(Wfc2, w2, FF_ * D_ / 4);

    // fused QKV projections (head-scatter, rounded store, q scaled)
    qkv_gemm_k<<<gQKV, blk, GEMM_SMEM_BYTES>>>(xr, wq, wk, wv, q, k, v);

    // attention
    flash_attn_mma_k<<<dim3(S_ / 64, B_ * H_), dim3(128)>>>(q, k, v, attn);

    // O projection + residual (fp32 x), LN1 (dual store: fp32 h + rounded hr)
    tf32gemm_k<false, true, false><<<gD, blk, GEMM_SMEM_BYTES>>>(attn, wo, x, tmp, M_, D_, D_);
    layernorm_k<<<M_, 256>>>(tmp, ln1g, ln1b, h, hr);

    // FFN: fc1 (+ReLU, rounded store), fc2 (+fp32 h residual), LN2 -> out
    tf32gemm_k<true, false, true><<<gF, blk, GEMM_SMEM_BYTES>>>(hr, w1, nullptr, ff, M_, FF_, D_);
    tf32gemm_k<false, true, false><<<gD, blk, GEMM_SMEM_BYTES>>>(ff, w2, h, tmp, M_, D_, FF_);
    layernorm_k<<<M_, 256>>>(tmp, ln2g, ln2b, out, nullptr);
}

// round 10
// speedup vs baseline: 4.4940x; 1.0413x over previous
#include <cuda_runtime.h>
#include <cuda_bf16.h>
#include <cstdint>

// Problem constants
#define B_  4
#define S_  2048
#define D_  1024
#define H_  16
#define DK_ 64
#define FF_ 4096
#define M_  (B_ * S_)   // 8192

// ---------------------------------------------------------------------------
// Scratch (device globals; no allocation allowed)
// ---------------------------------------------------------------------------
__device__ float g_q[M_ * D_];       // rounded + 0.125-scaled
__device__ float g_k[M_ * D_];       // rounded
__device__ float g_v[M_ * D_];       // rounded
__device__ float g_attn[M_ * D_];    // rounded (A of O-proj)
__device__ float g_tmp[M_ * D_];
__device__ float g_h[M_ * D_];       // fp32 (residual for fc2)
__device__ float g_hr[M_ * D_];      // rounded (A of fc1)
__device__ float g_ff[M_ * FF_];     // rounded (A of fc2)
__device__ float g_xr[M_ * D_];      // rounded x
__device__ float g_wq[D_ * D_];
__device__ float g_wk[D_ * D_];
__device__ float g_wv[D_ * D_];
__device__ float g_wo[D_ * D_];
__device__ float g_w1[D_ * FF_];
__device__ float g_w2[FF_ * D_];

__device__ __forceinline__ float to_tf32(float x) {
    float r;
    asm("cvt.rna.tf32.f32 %0, %1;" : "=f"(r) : "f"(x));
    return r;
}

__device__ __forceinline__ void mma_tf32(float* d, const float* a, const float* b) {
    asm volatile(
        "mma.sync.aligned.m16n8k8.row.col.f32.tf32.tf32.f32 "
        "{%0,%1,%2,%3}, {%4,%5,%6,%7}, {%8,%9}, {%0,%1,%2,%3};"
        : "+f"(d[0]), "+f"(d[1]), "+f"(d[2]), "+f"(d[3])
        : "r"(__float_as_uint(a[0])), "r"(__float_as_uint(a[1])),
          "r"(__float_as_uint(a[2])), "r"(__float_as_uint(a[3])),
          "r"(__float_as_uint(b[0])), "r"(__float_as_uint(b[1])));
}

#define CP16(dst, src) \
    asm volatile("cp.async.cg.shared.global [%0], [%1], 16;\n" :: "r"(dst), "l"(src))
#define CPCOMMIT() asm volatile("cp.async.commit_group;\n")
#define CPWAIT(n)  asm volatile("cp.async.wait_group %0;\n" :: "n"(n))

// ---------------------------------------------------------------------------
// Fused pre-round: tf32-round x + all 6 weights in one launch.
// Segment bounds are compile-time float4 counts.
// ---------------------------------------------------------------------------
#define N4_X   (M_ * D_ / 4)          // 2,097,152
#define N4_W   (D_ * D_ / 4)          //   262,144
#define N4_W1  (D_ * FF_ / 4)         // 1,048,576
#define N4_TOT (N4_X + 4 * N4_W + 2 * N4_W1)

__global__ __launch_bounds__(256) void roundall_k(
    const float* __restrict__ x,  const float* __restrict__ Wq,
    const float* __restrict__ Wk, const float* __restrict__ Wv,
    const float* __restrict__ Wo, const float* __restrict__ W1,
    const float* __restrict__ W2,
    float* __restrict__ xr, float* __restrict__ wq, float* __restrict__ wk,
    float* __restrict__ wv, float* __restrict__ wo, float* __restrict__ w1,
    float* __restrict__ w2)
{
    int i = blockIdx.x * 256 + threadIdx.x;
    if (i >= N4_TOT) return;
    const float4* src;
    float4* dst;
    int j = i;
    if (j < N4_X)                 { src = (const float4*)x  + j; dst = (float4*)xr + j; }
    else if ((j -= N4_X) < N4_W)  { src = (const float4*)Wq + j; dst = (float4*)wq + j; }
    else if ((j -= N4_W) < N4_W)  { src = (const float4*)Wk + j; dst = (float4*)wk + j; }
    else if ((j -= N4_W) < N4_W)  { src = (const float4*)Wv + j; dst = (float4*)wv + j; }
    else if ((j -= N4_W) < N4_W)  { src = (const float4*)Wo + j; dst = (float4*)wo + j; }
    else if ((j -= N4_W) < N4_W1) { src = (const float4*)W1 + j; dst = (float4*)w1 + j; }
    else { j -= N4_W1;              src = (const float4*)W2 + j; dst = (float4*)w2 + j; }
    float4 v = *src;
    float4 t;
    t.x = to_tf32(v.x); t.y = to_tf32(v.y);
    t.z = to_tf32(v.z); t.w = to_tf32(v.w);
    *dst = t;
}

// ---------------------------------------------------------------------------
// TF32 GEMM: 128x128 CTA tile, BK=32, 128 threads (4 warps), warp tile 64x64.
// 3-stage cp.async pipeline. Operands must be pre-rounded tf32 values.
// ---------------------------------------------------------------------------
#define AST (128 * 36)
#define BST (32 * 136)
#define GEMM_SMEM_BYTES ((3 * (AST + BST)) * 4)

template <bool RELU, bool RESID, bool HEADOUT, bool ROUND>
__device__ __forceinline__ void gemm_body(
    const float* __restrict__ A, const float* __restrict__ Bm,
    const float* __restrict__ Res, float* __restrict__ C,
    int M, int N, int K, float* smem, float outScale)
{
    float* Asb = smem;
    float* Bsb = smem + 3 * AST;

    const int tid  = threadIdx.x;
    const int lane = tid & 31;
    const int wid  = tid >> 5;
    const int wm   = wid & 1;
    const int wn   = wid >> 1;
    const int gid  = lane >> 2;
    const int qid  = lane & 3;

    const int m0 = blockIdx.y * 128;
    const int n0 = blockIdx.x * 128;

    const int aRow0 = tid >> 3;
    const int aCol  = (tid & 7) * 4;
    const int bRow0 = tid >> 5;
    const int bCol  = (tid & 31) * 4;

    const unsigned int aSm = (unsigned int)__cvta_generic_to_shared(Asb) + (aRow0 * 36 + aCol) * 4;
    const unsigned int bSm = (unsigned int)__cvta_generic_to_shared(Bsb) + (bRow0 * 136 + bCol) * 4;
    const float* Ag = A + (size_t)(m0 + aRow0) * K + aCol;
    const float* Bg = Bm + (size_t)bRow0 * N + n0 + bCol;

    auto issue = [&](int t) {
        const int st = t % 3;
        const unsigned int ad = aSm + st * (AST * 4);
        const unsigned int bd = bSm + st * (BST * 4);
        const float* As_g = Ag + t * 32;
        const float* Bs_g = Bg + (size_t)(t * 32) * N;
        #pragma unroll
        for (int i = 0; i < 8; i++)
            CP16(ad + i * (16 * 36 * 4), As_g + (size_t)(16 * i) * K);
        #pragma unroll
        for (int i = 0; i < 8; i++)
            CP16(bd + i * (4 * 136 * 4), Bs_g + (size_t)(4 * i) * N);
        CPCOMMIT();
    };

    float acc[4][8][4];
    #pragma unroll
    for (int i = 0; i < 4; i++)
        #pragma unroll
        for (int j = 0; j < 8; j++)
            #pragma unroll
            for (int r = 0; r < 4; r++) acc[i][j][r] = 0.f;

    const int nT = K / 32;
    issue(0);
    issue(1);

    for (int t = 0; t < nT; t++) {
        if (t + 1 < nT) { CPWAIT(1); } else { CPWAIT(0); }
        __syncthreads();
        if (t + 2 < nT) issue(t + 2);

        const int stA = (t % 3) * AST;
        const int stB = (t % 3) * BST;
        #pragma unroll
        for (int ks = 0; ks < 4; ks++) {
            const int kb = ks * 8;
            float af[4][4], bf[8][2];
            #pragma unroll
            for (int mt = 0; mt < 4; mt++) {
                const int r = wm * 64 + mt * 16 + gid;
                af[mt][0] = Asb[stA + r * 36 + kb + qid];
                af[mt][1] = Asb[stA + (r + 8) * 36 + kb + qid];
                af[mt][2] = Asb[stA + r * 36 + kb + qid + 4];
                af[mt][3] = Asb[stA + (r + 8) * 36 + kb + qid + 4];
            }
            #pragma unroll
            for (int nt = 0; nt < 8; nt++) {
                const int c = wn * 64 + nt * 8 + gid;
                bf[nt][0] = Bsb[stB + (kb + qid) * 136 + c];
                bf[nt][1] = Bsb[stB + (kb + qid + 4) * 136 + c];
            }
            #pragma unroll
            for (int mt = 0; mt < 4; mt++)
                #pragma unroll
                for (int nt = 0; nt < 8; nt++)
                    mma_tf32(acc[mt][nt], af[mt], bf[nt]);
        }
    }

    #pragma unroll
    for (int mt = 0; mt < 4; mt++) {
        #pragma unroll
        for (int nt = 0; nt < 8; nt++) {
            const int rBase = m0 + wm * 64 + mt * 16 + gid;
            const int cBase = n0 + wn * 64 + nt * 8 + qid * 2;
            #pragma unroll
            for (int half = 0; half < 2; half++) {
                const int m = rBase + half * 8;
                float v0 = acc[mt][nt][half * 2 + 0];
                float v1 = acc[mt][nt][half * 2 + 1];
                if (RELU)  { v0 = fmaxf(v0, 0.f); v1 = fmaxf(v1, 0.f); }
                if (RESID) {
                    const float* rp = Res + (size_t)m * N + cBase;
                    v0 += rp[0]; v1 += rp[1];
                }
                if (ROUND) {
                    v0 = to_tf32(v0 * outScale);
                    v1 = to_tf32(v1 * outScale);
                }
                if (HEADOUT) {
                    const int b = m >> 11, s = m & (S_ - 1);
                    const int h = cBase >> 6, d = cBase & (DK_ - 1);
                    float* dst = C + ((size_t)(b * H_ + h) * S_ + s) * DK_ + d;
                    dst[0] = v0; dst[1] = v1;
                } else {
                    float* dst = C + (size_t)m * N + cBase;
                    dst[0] = v0; dst[1] = v1;
                }
            }
        }
    }
}

// Fused QKV: blockIdx.z selects weight/output. Output rounded; q scaled by 0.125.
__global__ __launch_bounds__(128) void qkv_gemm_k(
    const float* __restrict__ x,
    const float* __restrict__ Wq, const float* __restrict__ Wk,
    const float* __restrict__ Wv,
    float* __restrict__ q, float* __restrict__ k, float* __restrict__ v)
{
    extern __shared__ float smem[];
    const float* W = (blockIdx.z == 0) ? Wq : (blockIdx.z == 1) ? Wk : Wv;
    float* C = (blockIdx.z == 0) ? q : (blockIdx.z == 1) ? k : v;
    const float sc = (blockIdx.z == 0) ? 0.125f : 1.0f;
    gemm_body<false, false, true, true>(x, W, nullptr, C, M_, D_, D_, smem, sc);
}

template <bool RELU, bool RESID, bool ROUND>
__global__ __launch_bounds__(128) void tf32gemm_k(
    const float* __restrict__ A, const float* __restrict__ Bm,
    const float* __restrict__ Res, float* __restrict__ C,
    int M, int N, int K)
{
    extern __shared__ float smem[];
    gemm_body<RELU, RESID, false, ROUND>(A, Bm, Res, C, M, N, K, smem, 1.0f);
}

// ---------------------------------------------------------------------------
// TF32 mma flash attention with 2-stage cp.async K/V pipeline.
// One block per (bh, q-tile of 64); 128 threads = 4 warps.
// Dynamic smem layout (floats):
//   Qs [64][68]    @ 0
//   Ks [2][32][68] @ 4352
//   Vs [2][32][72] @ 8704
//   Ps [64][36]    @ 13312     total 15616 floats = 62464 B
// ---------------------------------------------------------------------------
#define QS_OFF 0
#define KS_OFF 4352
#define VS_OFF 8704
#define PS_OFF 13312
#define ATTN_SMEM_BYTES (15616 * 4)

__global__ __launch_bounds__(128) void flash_attn_mma_k(
    const float* __restrict__ Q, const float* __restrict__ K,
    const float* __restrict__ V, float* __restrict__ O)
{
    extern __shared__ float sm[];
    float* Qs = sm + QS_OFF;
    float* Ks = sm + KS_OFF;
    float* Vs = sm + VS_OFF;
    float* Ps = sm + PS_OFF;

    const int tid  = threadIdx.x;
    const int lane = tid & 31;
    const int wid  = tid >> 5;
    const int gid  = lane >> 2;
    const int qid  = lane & 3;
    const int wq0  = wid * 16;

    const int qt = blockIdx.x;
    const int bh = blockIdx.y;

    const float* Qb = Q + ((size_t)bh * S_ + qt * 64) * DK_;
    const float* Kb = K + (size_t)bh * S_ * DK_;
    const float* Vb = V + (size_t)bh * S_ * DK_;

    const unsigned int kSm = (unsigned int)__cvta_generic_to_shared(Ks);
    const unsigned int vSm = (unsigned int)__cvta_generic_to_shared(Vs);
    const int ldR = tid >> 4;            // 0..7
    const int ldF = (tid & 15) << 2;     // 0..60

    auto issue = [&](int kt) {
        const int st = kt & 1;
        const float* Kp = Kb + (size_t)kt * 32 * DK_;
        const float* Vp = Vb + (size_t)kt * 32 * DK_;
        #pragma unroll
        for (int i = 0; i < 4; i++) {
            const int r = ldR + i * 8;
            CP16(kSm + (st * 2176 + r * 68 + ldF) * 4, Kp + r * DK_ + ldF);
            CP16(vSm + (st * 2304 + r * 72 + ldF) * 4, Vp + r * DK_ + ldF);
        }
        CPCOMMIT();
    };

    // Q tile (pre-rounded, pre-scaled) -> smem -> registers
    #pragma unroll
    for (int i = 0; i < 8; i++) {
        int idx = tid + i * 128;
        int r = idx >> 4, f = (idx & 15) << 2;
        *(float4*)&Qs[r * 68 + f] = *(const float4*)(Qb + r * DK_ + f);
    }
    issue(0);
    __syncthreads();

    float qf[8][4];
    #pragma unroll
    for (int ks = 0; ks < 8; ks++) {
        const int kb = ks * 8;
        qf[ks][0] = Qs[(wq0 + gid) * 68 + kb + qid];
        qf[ks][1] = Qs[(wq0 + gid + 8) * 68 + kb + qid];
        qf[ks][2] = Qs[(wq0 + gid) * 68 + kb + qid + 4];
        qf[ks][3] = Qs[(wq0 + gid + 8) * 68 + kb + qid + 4];
    }

    float oacc[8][4];
    #pragma unroll
    for (int nt = 0; nt < 8; nt++)
        #pragma unroll
        for (int r = 0; r < 4; r++) oacc[nt][r] = 0.f;
    float mrow[2] = {-1e30f, -1e30f};
    float lrow[2] = {0.f, 0.f};

    const int nKT = S_ / 32;
    for (int kt = 0; kt < nKT; kt++) {
        CPWAIT(0);            // tile kt landed
        __syncthreads();      // visible to all; all warps done with tile kt-1
        if (kt + 1 < nKT) issue(kt + 1);   // overlaps with compute below

        const int stK = (kt & 1) * 2176;
        const int stV = (kt & 1) * 2304;

        // S = Q K^T : 16 q x 32 keys, k = 64
        float sacc[4][4];
        #pragma unroll
        for (int nt = 0; nt < 4; nt++)
            #pragma unroll
            for (int r = 0; r < 4; r++) sacc[nt][r] = 0.f;

        #pragma unroll
        for (int ks = 0; ks < 8; ks++) {
            const int kb = ks * 8;
            #pragma unroll
            for (int nt = 0; nt < 4; nt++) {
                float bf[2];
                bf[0] = Ks[stK + (nt * 8 + gid) * 68 + kb + qid];
                bf[1] = Ks[stK + (nt * 8 + gid) * 68 + kb + qid + 4];
                mma_tf32(sacc[nt], qf[ks], bf);
            }
        }

        // online softmax
        #pragma unroll
        for (int i = 0; i < 2; i++) {
            const int b0 = i * 2;
            float tm = -1e30f;
            #pragma unroll
            for (int nt = 0; nt < 4; nt++)
                tm = fmaxf(tm, fmaxf(sacc[nt][b0], sacc[nt][b0 + 1]));
            tm = fmaxf(tm, __shfl_xor_sync(0xffffffffu, tm, 1));
            tm = fmaxf(tm, __shfl_xor_sync(0xffffffffu, tm, 2));
            float nm = fmaxf(mrow[i], tm);
            float fac = __expf(mrow[i] - nm);
            mrow[i] = nm;
            float rs = 0.f;
            #pragma unroll
            for (int nt = 0; nt < 4; nt++) {
                float p0 = __expf(sacc[nt][b0] - nm);
                float p1 = __expf(sacc[nt][b0 + 1] - nm);
                sacc[nt][b0] = p0; sacc[nt][b0 + 1] = p1;
                rs += p0 + p1;
            }
            rs += __shfl_xor_sync(0xffffffffu, rs, 1);
            rs += __shfl_xor_sync(0xffffffffu, rs, 2);
            lrow[i] = lrow[i] * fac + rs;
            #pragma unroll
            for (int nt = 0; nt < 8; nt++) {
                oacc[nt][b0] *= fac;
                oacc[nt][b0 + 1] *= fac;
            }
        }

        // write P slab (own warp rows only)
        #pragma unroll
        for (int nt = 0; nt < 4; nt++) {
            *(float2*)&Ps[(wq0 + gid) * 36 + nt * 8 + qid * 2] =
                make_float2(to_tf32(sacc[nt][0]), to_tf32(sacc[nt][1]));
            *(float2*)&Ps[(wq0 + gid + 8) * 36 + nt * 8 + qid * 2] =
                make_float2(to_tf32(sacc[nt][2]), to_tf32(sacc[nt][3]));
        }
        __syncwarp();

        // O += P V : 16 q x 64 d, k = 32 keys
        #pragma unroll
        for (int ks = 0; ks < 4; ks++) {
            const int kb = ks * 8;
            float af[4];
            af[0] = Ps[(wq0 + gid) * 36 + kb + qid];
            af[1] = Ps[(wq0 + gid + 8) * 36 + kb + qid];
            af[2] = Ps[(wq0 + gid) * 36 + kb + qid + 4];
            af[3] = Ps[(wq0 + gid + 8) * 36 + kb + qid + 4];
            #pragma unroll
            for (int nt = 0; nt < 8; nt++) {
                float bf[2];
                bf[0] = Vs[stV + (kb + qid) * 72 + nt * 8 + gid];
                bf[1] = Vs[stV + (kb + qid + 4) * 72 + nt * 8 + gid];
                mma_tf32(oacc[nt], af, bf);
            }
        }
    }

    // epilogue: normalize, round (A-operand of O-proj), scatter
    const int b = bh >> 4, h = bh & 15;
    #pragma unroll
    for (int i = 0; i < 2; i++) {
        float inv = 1.0f / lrow[i];
        int row = b * S_ + qt * 64 + wq0 + gid + i * 8;
        float* dst = O + (size_t)row * D_ + h * DK_;
        #pragma unroll
        for (int nt = 0; nt < 8; nt++) {
            *(float2*)&dst[nt * 8 + qid * 2] =
                make_float2(to_tf32(oacc[nt][i * 2] * inv),
                            to_tf32(oacc[nt][i * 2 + 1] * inv));
        }
    }
}

// ---------------------------------------------------------------------------
// LayerNorm: one block (256 threads) per row of 1024.
// Optionally writes a tf32-rounded second copy (A-operand for next GEMM).
// ---------------------------------------------------------------------------
__global__ __launch_bounds__(256) void layernorm_k(
    const float* __restrict__ X, const float* __restrict__ gam,
    const float* __restrict__ bet, float* __restrict__ Y,
    float* __restrict__ Yr)
{
    const int row = blockIdx.x;
    const int tid = threadIdx.x;
    float4 v = *(const float4*)(X + (size_t)row * D_ + tid * 4);
    float s = v.x + v.y + v.z + v.w;
    float q = v.x * v.x + v.y * v.y + v.z * v.z + v.w * v.w;
    #pragma unroll
    for (int off = 16; off >= 1; off >>= 1) {
        s += __shfl_xor_sync(0xffffffffu, s, off);
        q += __shfl_xor_sync(0xffffffffu, q, off);
    }
    __shared__ float ss[8], sq[8];
    if ((tid & 31) == 0) { ss[tid >> 5] = s; sq[tid >> 5] = q; }
    __syncthreads();
    float ts = 0.f, tq = 0.f;
    #pragma unroll
    for (int i = 0; i < 8; i++) { ts += ss[i]; tq += sq[i]; }
    const float mu = ts * (1.0f / D_);
    const float var = tq * (1.0f / D_) - mu * mu;
    const float rstd = rsqrtf(var + 1e-5f);
    float4 g4 = *(const float4*)(gam + tid * 4);
    float4 b4 = *(const float4*)(bet + tid * 4);
    float4 y;
    y.x = (v.x - mu) * rstd * g4.x + b4.x;
    y.y = (v.y - mu) * rstd * g4.y + b4.y;
    y.z = (v.z - mu) * rstd * g4.z + b4.z;
    y.w = (v.w - mu) * rstd * g4.w + b4.w;
    *(float4*)(Y + (size_t)row * D_ + tid * 4) = y;
    if (Yr) {
        float4 r;
        r.x = to_tf32(y.x); r.y = to_tf32(y.y);
        r.z = to_tf32(y.z); r.w = to_tf32(y.w);
        *(float4*)(Yr + (size_t)row * D_ + tid * 4) = r;
    }
}

// ---------------------------------------------------------------------------
// Launch
// ---------------------------------------------------------------------------
extern "C" void kernel_launch(void* const* d_in, const int* in_sizes, int n_in,
                              void* d_out, int out_size)
{
    const float* x     = (const float*)d_in[0];
    const float* Wq    = (const float*)d_in[1];
    const float* Wk    = (const float*)d_in[2];
    const float* Wv    = (const float*)d_in[3];
    const float* Wo    = (const float*)d_in[4];
    const float* Wfc1  = (const float*)d_in[5];
    const float* Wfc2  = (const float*)d_in[6];
    const float* ln1g  = (const float*)d_in[7];
    const float* ln1b  = (const float*)d_in[8];
    const float* ln2g  = (const float*)d_in[9];
    const float* ln2b  = (const float*)d_in[10];
    float* out = (float*)d_out;

    float *q, *k, *v, *attn, *tmp, *h, *hr, *ff;
    float *xr, *wq, *wk, *wv, *wo, *w1, *w2;
    cudaGetSymbolAddress((void**)&q,    g_q);
    cudaGetSymbolAddress((void**)&k,    g_k);
    cudaGetSymbolAddress((void**)&v,    g_v);
    cudaGetSymbolAddress((void**)&attn, g_attn);
    cudaGetSymbolAddress((void**)&tmp,  g_tmp);
    cudaGetSymbolAddress((void**)&h,    g_h);
    cudaGetSymbolAddress((void**)&hr,   g_hr);
    cudaGetSymbolAddress((void**)&ff,   g_ff);
    cudaGetSymbolAddress((void**)&xr,   g_xr);
    cudaGetSymbolAddress((void**)&wq,   g_wq);
    cudaGetSymbolAddress((void**)&wk,   g_wk);
    cudaGetSymbolAddress((void**)&wv,   g_wv);
    cudaGetSymbolAddress((void**)&wo,   g_wo);
    cudaGetSymbolAddress((void**)&w1,   g_w1);
    cudaGetSymbolAddress((void**)&w2,   g_w2);

    cudaFuncSetAttribute(qkv_gemm_k,
        cudaFuncAttributeMaxDynamicSharedMemorySize, GEMM_SMEM_BYTES);
    cudaFuncSetAttribute(tf32gemm_k<false, true, false>,
        cudaFuncAttributeMaxDynamicSharedMemorySize, GEMM_SMEM_BYTES);
    cudaFuncSetAttribute(tf32gemm_k<true, false, true>,
        cudaFuncAttributeMaxDynamicSharedMemorySize, GEMM_SMEM_BYTES);
    cudaFuncSetAttribute(flash_attn_mma_k,
        cudaFuncAttributeMaxDynamicSharedMemorySize, ATTN_SMEM_BYTES);

    dim3 blk(128);
    dim3 gQKV(D_ / 128, M_ / 128, 3);   // (8, 64, 3)
    dim3 gD(D_ / 128, M_ / 128);        // (8, 64)
    dim3 gF(FF_ / 128, M_ / 128);       // (32, 64)

    // pre-round x and all weights (single launch)
    roundall_k<<<(N4_TOT + 255) / 256, 256>>>(
        x, Wq, Wk, Wv, Wo, Wfc1, Wfc2, xr, wq, wk, wv, wo, w1, w2);

    // fused QKV projections (head-scatter, rounded store, q scaled)
    qkv_gemm_k<<<gQKV, blk, GEMM_SMEM_BYTES>>>(xr, wq, wk, wv, q, k, v);

    // attention (2-stage cp.async pipeline)
    flash_attn_mma_k<<<dim3(S_ / 64, B_ * H_), dim3(128), ATTN_SMEM_BYTES>>>(q, k, v, attn);

    // O projection + residual (fp32 x), LN1 (dual store: fp32 h + rounded hr)
    tf32gemm_k<false, true, false><<<gD, blk, GEMM_SMEM_BYTES>>>(attn, wo, x, tmp, M_, D_, D_);
    layernorm_k<<<M_, 256>>>(tmp, ln1g, ln1b, h, hr);

    // FFN: fc1 (+ReLU, rounded store), fc2 (+fp32 h residual), LN2 -> out
    tf32gemm_k<true, false, true><<<gF, blk, GEMM_SMEM_BYTES>>>(hr, w1, nullptr, ff, M_, FF_, D_);
    tf32gemm_k<false, true, false><<<gD, blk, GEMM_SMEM_BYTES>>>(ff, w2, h, tmp, M_, D_, FF_);
    layernorm_k<<<M_, 256>>>(tmp, ln2g, ln2b, out, nullptr);
}